// round 2
// baseline (speedup 1.0000x reference)
#include <cuda_runtime.h>
#include <math.h>

#define TOK   18464          // B*S = 32*577
#define DMODEL 768
#define HEADS  12
#define DH     64
#define SEQ    577
#define BATCH  32
#define FFDIM  3072

// ---------------- static scratch (no allocations allowed) ----------------
// g_big is overlaid:
//   phase A (steps 2-4): [q | k | v | ctx]  4 x TOK*DMODEL floats
//   phase B (steps 6-7): [ffn]              TOK*FFDIM floats (= 4 x TOK*DMODEL)
// q/k/v dead after attention, ctx dead after Wo GEMM, ffn written after that -> safe.
__device__ float g_big[(size_t)TOK * FFDIM];
__device__ float g_h  [(size_t)TOK * DMODEL];   // LN output (reused LN1/LN2)

// ---------------- LayerNorm: one block per token ----------------
__global__ void ln_kernel(const float* __restrict__ x, const float* __restrict__ w,
                          const float* __restrict__ b, float* __restrict__ out) {
    int t = blockIdx.x;
    const float* xr = x + (size_t)t * DMODEL;
    float* orow = out + (size_t)t * DMODEL;
    float v[3];
    float s = 0.f, ss = 0.f;
#pragma unroll
    for (int i = 0; i < 3; i++) {
        v[i] = xr[threadIdx.x + i * 256];
        s += v[i];
        ss += v[i] * v[i];
    }
    __shared__ float red[16];
#pragma unroll
    for (int o = 16; o; o >>= 1) {
        s  += __shfl_xor_sync(~0u, s,  o);
        ss += __shfl_xor_sync(~0u, ss, o);
    }
    int wid = threadIdx.x >> 5, lid = threadIdx.x & 31;
    if (lid == 0) { red[wid] = s; red[8 + wid] = ss; }
    __syncthreads();
    s = 0.f; ss = 0.f;
#pragma unroll
    for (int i = 0; i < 8; i++) { s += red[i]; ss += red[8 + i]; }
    float mean = s * (1.0f / DMODEL);
    float var  = ss * (1.0f / DMODEL) - mean * mean;
    float rstd = rsqrtf(var + 1e-5f);
#pragma unroll
    for (int i = 0; i < 3; i++) {
        int d = threadIdx.x + i * 256;
        orow[d] = (v[i] - mean) * rstd * w[d] + b[d];
    }
}

// ---------------- SGEMM: C[M,N] = A[M,K] @ W + bias (+resid / gelu) ----------------
// EPI: 0 = +bias, 1 = +bias+resid, 2 = gelu(+bias)
// BHEADED: W is (H, K, 64) -> logical column n = h*64+e
template<int EPI, int BHEADED>
__global__ __launch_bounds__(256, 2)
void sgemm_kernel(const float* __restrict__ A, const float* __restrict__ W,
                  const float* __restrict__ bias, const float* __restrict__ resid,
                  float* __restrict__ C, int M, int N, int K) {
    __shared__ __align__(16) float As[8][128];
    __shared__ __align__(16) float Bs[8][128];
    int m0 = blockIdx.y * 128, n0 = blockIdx.x * 128;
    int tid = threadIdx.x;
    int tx = tid & 15, ty = tid >> 4;
    float acc[8][8];
#pragma unroll
    for (int i = 0; i < 8; i++)
#pragma unroll
        for (int j = 0; j < 8; j++) acc[i][j] = 0.f;

    int a_row = tid >> 1, a_k = (tid & 1) * 4;
    int b_k = tid >> 5, b_n = (tid & 31) * 4;
    bool a_ok = (m0 + a_row) < M;
    const float* Aptr = A + (size_t)(m0 + a_row) * K + a_k;

    for (int k0 = 0; k0 < K; k0 += 8) {
        float4 av = a_ok ? *(const float4*)(Aptr + k0) : make_float4(0.f, 0.f, 0.f, 0.f);
        float4 bv;
        if (BHEADED) {
            int n = n0 + b_n;
            bv = *(const float4*)(W + (size_t)(n >> 6) * K * 64 + (size_t)(k0 + b_k) * 64 + (n & 63));
        } else {
            bv = *(const float4*)(W + (size_t)(k0 + b_k) * N + n0 + b_n);
        }
        __syncthreads();
        As[a_k + 0][a_row] = av.x;
        As[a_k + 1][a_row] = av.y;
        As[a_k + 2][a_row] = av.z;
        As[a_k + 3][a_row] = av.w;
        *(float4*)&Bs[b_k][b_n] = bv;
        __syncthreads();
#pragma unroll
        for (int k = 0; k < 8; k++) {
            float a[8], b[8];
            *(float4*)(a)     = *(const float4*)&As[k][ty * 8];
            *(float4*)(a + 4) = *(const float4*)&As[k][ty * 8 + 4];
            *(float4*)(b)     = *(const float4*)&Bs[k][tx * 8];
            *(float4*)(b + 4) = *(const float4*)&Bs[k][tx * 8 + 4];
#pragma unroll
            for (int i = 0; i < 8; i++)
#pragma unroll
                for (int j = 0; j < 8; j++)
                    acc[i][j] += a[i] * b[j];
        }
    }

#pragma unroll
    for (int i = 0; i < 8; i++) {
        int m = m0 + ty * 8 + i;
        if (m < M) {
            float* crow = C + (size_t)m * N + n0 + tx * 8;
            const float* rrow = (EPI == 1) ? (resid + (size_t)m * N + n0 + tx * 8) : nullptr;
#pragma unroll
            for (int j = 0; j < 8; j++) {
                float val = acc[i][j] + bias[n0 + tx * 8 + j];
                if (EPI == 1) val += rrow[j];
                if (EPI == 2) val = 0.5f * val * (1.0f + erff(val * 0.70710678118654752f));
                crow[j] = val;
            }
        }
    }
}

// ---------------- Flash attention: block = 64 query rows of one (b,h) ----------------
// Thread layout: rg = tid/16 (4 rows each), kg = tid%16 (4 keys / 4 out-dims each)
__global__ __launch_bounds__(256)
void attn_kernel(const float* __restrict__ q, const float* __restrict__ k,
                 const float* __restrict__ v, float* __restrict__ ctx) {
    __shared__ __align__(16) float Qt [64][64];  // [d][r]
    __shared__ __align__(16) float KtP[64][64];  // Kt[d][c], reused as Pt[c][r]
    __shared__ __align__(16) float Vs [64][64];  // [c][e]

    int bh = blockIdx.y;
    int b = bh / HEADS, h = bh % HEADS;
    int q0 = blockIdx.x * 64;
    int tid = threadIdx.x;
    int rg = tid >> 4, kg = tid & 15;
    int r0 = rg * 4, c0 = kg * 4;
    size_t base = (size_t)b * SEQ * DMODEL + h * DH;

    // load Q tile transposed
    {
        int c = tid >> 2, el = tid & 3;
        int s = q0 + c;
        const float* qp = q + base + (size_t)s * DMODEL;
#pragma unroll
        for (int jj = 0; jj < 4; jj++) {
            int e0 = el * 4 + jj * 16;
            float4 vv = (s < SEQ) ? *(const float4*)(qp + e0) : make_float4(0.f, 0.f, 0.f, 0.f);
            Qt[e0 + 0][c] = vv.x; Qt[e0 + 1][c] = vv.y;
            Qt[e0 + 2][c] = vv.z; Qt[e0 + 3][c] = vv.w;
        }
    }

    float m[4], l[4], O[4][4];
#pragma unroll
    for (int i = 0; i < 4; i++) {
        m[i] = -1e30f; l[i] = 0.f;
#pragma unroll
        for (int j = 0; j < 4; j++) O[i][j] = 0.f;
    }

    const int NT = (SEQ + 63) / 64;
    for (int kt = 0; kt < NT; kt++) {
        int kbase = kt * 64;
        __syncthreads();   // prior iteration done with KtP/Vs
        {
            int c = tid >> 2, el = tid & 3;
            int s = kbase + c;
            const float* kp = k + base + (size_t)s * DMODEL;
            const float* vp = v + base + (size_t)s * DMODEL;
#pragma unroll
            for (int jj = 0; jj < 4; jj++) {
                int e0 = el * 4 + jj * 16;
                float4 kv = (s < SEQ) ? *(const float4*)(kp + e0) : make_float4(0.f, 0.f, 0.f, 0.f);
                KtP[e0 + 0][c] = kv.x; KtP[e0 + 1][c] = kv.y;
                KtP[e0 + 2][c] = kv.z; KtP[e0 + 3][c] = kv.w;
                float4 vv = (s < SEQ) ? *(const float4*)(vp + e0) : make_float4(0.f, 0.f, 0.f, 0.f);
                *(float4*)&Vs[c][e0] = vv;
            }
        }
        __syncthreads();

        // scores: sc[i][j] = Q[r0+i] . K[c0+j]
        float sc[4][4];
#pragma unroll
        for (int i = 0; i < 4; i++)
#pragma unroll
            for (int j = 0; j < 4; j++) sc[i][j] = 0.f;
#pragma unroll 8
        for (int d = 0; d < 64; d++) {
            float4 qv = *(const float4*)&Qt[d][r0];
            float4 kv = *(const float4*)&KtP[d][c0];
            float qa[4] = {qv.x, qv.y, qv.z, qv.w};
            float ka[4] = {kv.x, kv.y, kv.z, kv.w};
#pragma unroll
            for (int i = 0; i < 4; i++)
#pragma unroll
                for (int j = 0; j < 4; j++)
                    sc[i][j] += qa[i] * ka[j];
        }
        // scale + mask
#pragma unroll
        for (int j = 0; j < 4; j++) {
            bool valid = (kbase + c0 + j) < SEQ;
#pragma unroll
            for (int i = 0; i < 4; i++)
                sc[i][j] = valid ? sc[i][j] * 0.125f : -1e30f;
        }
        // online softmax per row (reduce across the 16 kg lanes of this rg)
#pragma unroll
        for (int i = 0; i < 4; i++) {
            float mx = sc[i][0];
#pragma unroll
            for (int j = 1; j < 4; j++) mx = fmaxf(mx, sc[i][j]);
#pragma unroll
            for (int o = 1; o < 16; o <<= 1) mx = fmaxf(mx, __shfl_xor_sync(~0u, mx, o));
            float mn = fmaxf(m[i], mx);
            float corr = __expf(m[i] - mn);
            m[i] = mn;
            float ls = 0.f;
#pragma unroll
            for (int j = 0; j < 4; j++) {
                sc[i][j] = __expf(sc[i][j] - mn);
                ls += sc[i][j];
            }
#pragma unroll
            for (int o = 1; o < 16; o <<= 1) ls += __shfl_xor_sync(~0u, ls, o);
            l[i] = l[i] * corr + ls;
#pragma unroll
            for (int j = 0; j < 4; j++) O[i][j] *= corr;
        }
        __syncthreads();   // done reading Kt
        // write P transposed: Pt[c][r]
#pragma unroll
        for (int j = 0; j < 4; j++)
#pragma unroll
            for (int i = 0; i < 4; i++)
                KtP[c0 + j][r0 + i] = sc[i][j];
        __syncthreads();
        // O[i][j] += sum_c P[r0+i][c] * V[c][c0+j]
#pragma unroll 8
        for (int c = 0; c < 64; c++) {
            float4 pv = *(const float4*)&KtP[c][r0];
            float4 vv = *(const float4*)&Vs[c][c0];
            float pa[4] = {pv.x, pv.y, pv.z, pv.w};
            float va[4] = {vv.x, vv.y, vv.z, vv.w};
#pragma unroll
            for (int i = 0; i < 4; i++)
#pragma unroll
                for (int j = 0; j < 4; j++)
                    O[i][j] += pa[i] * va[j];
        }
    }

#pragma unroll
    for (int i = 0; i < 4; i++) {
        int s = q0 + r0 + i;
        if (s < SEQ) {
            float inv = 1.0f / l[i];
            float4 o4 = make_float4(O[i][0] * inv, O[i][1] * inv, O[i][2] * inv, O[i][3] * inv);
            *(float4*)(ctx + base + (size_t)s * DMODEL + c0) = o4;
        }
    }
}

// ---------------- launch ----------------
extern "C" void kernel_launch(void* const* d_in, const int* in_sizes, int n_in,
                              void* d_out, int out_size) {
    const float* x    = (const float*)d_in[0];
    const float* ln1w = (const float*)d_in[1];
    const float* ln1b = (const float*)d_in[2];
    const float* Wq   = (const float*)d_in[3];
    const float* bq   = (const float*)d_in[4];
    const float* Wk   = (const float*)d_in[5];
    const float* bk   = (const float*)d_in[6];
    const float* Wv   = (const float*)d_in[7];
    const float* bv   = (const float*)d_in[8];
    const float* Wo   = (const float*)d_in[9];
    const float* bo   = (const float*)d_in[10];
    const float* ln2w = (const float*)d_in[11];
    const float* ln2b = (const float*)d_in[12];
    const float* W1   = (const float*)d_in[13];
    const float* b1   = (const float*)d_in[14];
    const float* W2   = (const float*)d_in[15];
    const float* b2   = (const float*)d_in[16];
    float* out = (float*)d_out;

    static float* s_big = nullptr;
    static float* s_h   = nullptr;
    if (!s_big) {
        cudaGetSymbolAddress((void**)&s_big, g_big);
        cudaGetSymbolAddress((void**)&s_h,   g_h);
    }
    const size_t TD = (size_t)TOK * DMODEL;
    float* h  = s_h;
    float* qb = s_big;            // overlay slice 0
    float* kb = s_big + TD;       // overlay slice 1
    float* vb = s_big + 2 * TD;   // overlay slice 2
    float* cb = s_big + 3 * TD;   // overlay slice 3
    float* fb = s_big;            // full buffer (phase B, after cb is dead)

    dim3 gD(DMODEL / 128, (TOK + 127) / 128);   // N=768 tiles
    dim3 gF(FFDIM  / 128, (TOK + 127) / 128);   // N=3072 tiles

    // 1. LN1
    ln_kernel<<<TOK, 256>>>(x, ln1w, ln1b, h);
    // 2. Q/K/V projections (headed weight layout)
    sgemm_kernel<0, 1><<<gD, 256>>>(h, Wq, bq, nullptr, qb, TOK, DMODEL, DMODEL);
    sgemm_kernel<0, 1><<<gD, 256>>>(h, Wk, bk, nullptr, kb, TOK, DMODEL, DMODEL);
    sgemm_kernel<0, 1><<<gD, 256>>>(h, Wv, bv, nullptr, vb, TOK, DMODEL, DMODEL);
    // 3. attention
    attn_kernel<<<dim3((SEQ + 63) / 64, BATCH * HEADS), 256>>>(qb, kb, vb, cb);
    // 4. output projection + residual -> d_out = x1
    sgemm_kernel<1, 0><<<gD, 256>>>(cb, Wo, bo, x, out, TOK, DMODEL, DMODEL);
    // 5. LN2
    ln_kernel<<<TOK, 256>>>(out, ln2w, ln2b, h);
    // 6. MLP up + exact GELU (overwrites q/k/v/ctx region — all dead now)
    sgemm_kernel<2, 0><<<gF, 256>>>(h, W1, b1, nullptr, fb, TOK, FFDIM, DMODEL);
    // 7. MLP down + residual (accumulates into d_out)
    sgemm_kernel<1, 0><<<gD, 256>>>(fb, W2, b2, out, out, TOK, DMODEL, FFDIM);
}

// round 7
// speedup vs baseline: 1.9055x; 1.9055x over previous
#include <cuda_runtime.h>
#include <math.h>
#include <stdint.h>

#define TOK    18464         // B*S = 32*577
#define DMODEL 768
#define HEADS  12
#define DH     64
#define SEQ    577
#define BATCH  32
#define FFDIM  3072

// ---------------- static scratch (no allocations allowed) ----------------
// g_big overlay: phase A [q|k|v|ctx] 4x TOK*DMODEL ; phase B [ffn] TOK*FFDIM
__device__ float g_big[(size_t)TOK * FFDIM];
__device__ float g_h  [(size_t)TOK * DMODEL];
// transposed tf32-rounded weights: WqT,WkT,WvT,WoT (768x768), W1T (3072x768), W2T (768x3072)
__device__ float g_wt [4 * 768 * 768 + 2 * 768 * 3072];

// ---------------- helpers ----------------
__device__ __forceinline__ uint32_t smem_u32(const void* p) {
    uint32_t a;
    asm("{ .reg .u64 t; cvta.to.shared.u64 t, %1; cvt.u32.u64 %0, t; }" : "=r"(a) : "l"(p));
    return a;
}
__device__ __forceinline__ float rn_tf32(float x) {
    uint32_t u;
    asm("cvt.rna.tf32.f32 %0, %1;" : "=r"(u) : "f"(x));
    return __uint_as_float(u);
}
__device__ __forceinline__ void cp16(uint32_t dst, const void* src, int sz) {
    asm volatile("cp.async.cg.shared.global [%0], [%1], 16, %2;"
                 :: "r"(dst), "l"(src), "r"(sz) : "memory");
}
__device__ __forceinline__ void cp_commit() {
    asm volatile("cp.async.commit_group;" ::: "memory");
}
template<int N>
__device__ __forceinline__ void cp_wait() {
    asm volatile("cp.async.wait_group %0;" :: "n"(N) : "memory");
}
__device__ __forceinline__ void mma_tf32(float* d, const float* a, const float* b) {
    asm volatile(
        "mma.sync.aligned.m16n8k8.row.col.f32.tf32.tf32.f32 "
        "{%0,%1,%2,%3}, {%4,%5,%6,%7}, {%8,%9}, {%0,%1,%2,%3};"
        : "+f"(d[0]), "+f"(d[1]), "+f"(d[2]), "+f"(d[3])
        : "r"(__float_as_uint(a[0])), "r"(__float_as_uint(a[1])),
          "r"(__float_as_uint(a[2])), "r"(__float_as_uint(a[3])),
          "r"(__float_as_uint(b[0])), "r"(__float_as_uint(b[1])));
}

// ---------------- LayerNorm (tf32-rounded output) ----------------
__global__ void ln_kernel(const float* __restrict__ x, const float* __restrict__ w,
                          const float* __restrict__ b, float* __restrict__ out) {
    int t = blockIdx.x;
    const float* xr = x + (size_t)t * DMODEL;
    float* orow = out + (size_t)t * DMODEL;
    float v[3];
    float s = 0.f, ss = 0.f;
#pragma unroll
    for (int i = 0; i < 3; i++) {
        v[i] = xr[threadIdx.x + i * 256];
        s += v[i]; ss += v[i] * v[i];
    }
    __shared__ float red[16];
#pragma unroll
    for (int o = 16; o; o >>= 1) {
        s  += __shfl_xor_sync(~0u, s,  o);
        ss += __shfl_xor_sync(~0u, ss, o);
    }
    int wid = threadIdx.x >> 5, lid = threadIdx.x & 31;
    if (lid == 0) { red[wid] = s; red[8 + wid] = ss; }
    __syncthreads();
    s = 0.f; ss = 0.f;
#pragma unroll
    for (int i = 0; i < 8; i++) { s += red[i]; ss += red[8 + i]; }
    float mean = s * (1.0f / DMODEL);
    float var  = ss * (1.0f / DMODEL) - mean * mean;
    float rstd = rsqrtf(var + 1e-5f);
#pragma unroll
    for (int i = 0; i < 3; i++) {
        int d = threadIdx.x + i * 256;
        orow[d] = rn_tf32((v[i] - mean) * rstd * w[d] + b[d]);
    }
}

// ---------------- weight transpose (fp32 [K][N] -> tf32-rounded [N][K]) ----------------
__global__ void transpose_w(const float* __restrict__ W, float* __restrict__ WT,
                            int K, int N) {
    __shared__ float t[32][33];
    int k0 = blockIdx.y * 32, n0 = blockIdx.x * 32;
#pragma unroll
    for (int j = 0; j < 4; j++)
        t[threadIdx.y + 8 * j][threadIdx.x] =
            W[(size_t)(k0 + threadIdx.y + 8 * j) * N + n0 + threadIdx.x];
    __syncthreads();
#pragma unroll
    for (int j = 0; j < 4; j++)
        WT[(size_t)(n0 + threadIdx.y + 8 * j) * K + k0 + threadIdx.x] =
            rn_tf32(t[threadIdx.x][threadIdx.y + 8 * j]);
}
// headed: W is (H, K, 64); logical col n = h*64+e
__global__ void transpose_wh(const float* __restrict__ W, float* __restrict__ WT, int K) {
    __shared__ float t[32][33];
    int k0 = blockIdx.y * 32, n0 = blockIdx.x * 32;
    int n = n0 + threadIdx.x;
    const float* Wp = W + (size_t)(n >> 6) * K * 64 + (n & 63);
#pragma unroll
    for (int j = 0; j < 4; j++)
        t[threadIdx.y + 8 * j][threadIdx.x] = Wp[(size_t)(k0 + threadIdx.y + 8 * j) * 64];
    __syncthreads();
#pragma unroll
    for (int j = 0; j < 4; j++)
        WT[(size_t)(n0 + threadIdx.y + 8 * j) * K + k0 + threadIdx.x] =
            rn_tf32(t[threadIdx.x][threadIdx.y + 8 * j]);
}

// ---------------- TF32 warp-MMA GEMM: C[M,N] = A[M,K] @ Bt[N,K]^T ----------------
// Tile 128x128x32, 8 warps (2x4), warp tile 64x32 = 4x4 m16n8k8.
// EPI: 0 = +bias ; 1 = +bias+resid ; 2 = gelu(+bias), tf32-rounded
#define GEMM_SMEM 73728   // 2 buffers * (As 128*36 + Bs 128*36) * 4B

template<int EPI>
__global__ __launch_bounds__(256, 2)
void mma_gemm(const float* __restrict__ A, const float* __restrict__ Bt,
              const float* __restrict__ bias, const float* __restrict__ resid,
              float* __restrict__ C, int M, int N, int K) {
    extern __shared__ float sm[];
    uint32_t sb = smem_u32(sm);
    int tid = threadIdx.x;
    int wid = tid >> 5, lane = tid & 31;
    int g = lane >> 2, t4 = lane & 3;
    int wm = wid >> 2, wn = wid & 3;
    int m0 = blockIdx.y * 128, n0 = blockIdx.x * 128;

    // global->smem mapping: 2 threads per row, 16 floats each
    int lrow = tid >> 1;
    int lcol = (tid & 1) * 16;
    bool aok = (m0 + lrow) < M;
    const float* Aptr = aok ? (A + (size_t)(m0 + lrow) * K + lcol) : A;
    const float* Bptr = Bt + (size_t)(n0 + lrow) * K + lcol;
    int asz = aok ? 16 : 0;
    uint32_t sa = sb + (uint32_t)(lrow * 36 + lcol) * 4;   // +buf*36864
    uint32_t sbB = sa + 18432;

    float acc[4][4][4];
#pragma unroll
    for (int mi = 0; mi < 4; mi++)
#pragma unroll
        for (int ni = 0; ni < 4; ni++)
#pragma unroll
            for (int j = 0; j < 4; j++) acc[mi][ni][j] = 0.f;

    const int nch = K / 32;

    // prefetch chunk 0 -> buf 0
#pragma unroll
    for (int q = 0; q < 4; q++) {
        cp16(sa  + q * 16, Aptr + q * 4, asz);
        cp16(sbB + q * 16, Bptr + q * 4, 16);
    }
    cp_commit();

    for (int i = 0; i < nch; i++) {
        if (i + 1 < nch) {
            uint32_t off = ((i + 1) & 1) * 36864u;
#pragma unroll
            for (int q = 0; q < 4; q++) {
                cp16(sa  + off + q * 16, Aptr + (i + 1) * 32 + q * 4, asz);
                cp16(sbB + off + q * 16, Bptr + (i + 1) * 32 + q * 4, 16);
            }
            cp_commit();
            cp_wait<1>();
        } else {
            cp_wait<0>();
        }
        __syncthreads();

        const float* As = sm + (i & 1) * 9216;
        const float* Bs = As + 4608;
#pragma unroll
        for (int kk = 0; kk < 4; kk++) {
            float af[4][4], bf[4][2];
#pragma unroll
            for (int mi = 0; mi < 4; mi++) {
                int r = wm * 64 + mi * 16 + g;
                af[mi][0] = As[r * 36 + kk * 8 + t4];
                af[mi][1] = As[(r + 8) * 36 + kk * 8 + t4];
                af[mi][2] = As[r * 36 + kk * 8 + t4 + 4];
                af[mi][3] = As[(r + 8) * 36 + kk * 8 + t4 + 4];
            }
#pragma unroll
            for (int ni = 0; ni < 4; ni++) {
                int c = wn * 32 + ni * 8 + g;
                bf[ni][0] = Bs[c * 36 + kk * 8 + t4];
                bf[ni][1] = Bs[c * 36 + kk * 8 + t4 + 4];
            }
#pragma unroll
            for (int mi = 0; mi < 4; mi++)
#pragma unroll
                for (int ni = 0; ni < 4; ni++)
                    mma_tf32(acc[mi][ni], af[mi], bf[ni]);
        }
        __syncthreads();
    }

    // epilogue
#pragma unroll
    for (int mi = 0; mi < 4; mi++) {
        int r1 = m0 + wm * 64 + mi * 16 + g;
        int r2 = r1 + 8;
#pragma unroll
        for (int ni = 0; ni < 4; ni++) {
            int col = n0 + wn * 32 + ni * 8 + 2 * t4;
            float2 bs = *(const float2*)(bias + col);
#pragma unroll
            for (int hrow = 0; hrow < 2; hrow++) {
                int r = hrow ? r2 : r1;
                if (r < M) {
                    float v0 = acc[mi][ni][hrow * 2 + 0] + bs.x;
                    float v1 = acc[mi][ni][hrow * 2 + 1] + bs.y;
                    if (EPI == 1) {
                        float2 rv = *(const float2*)(resid + (size_t)r * N + col);
                        v0 += rv.x; v1 += rv.y;
                    }
                    if (EPI == 2) {
                        v0 = rn_tf32(0.5f * v0 * (1.0f + erff(v0 * 0.70710678f)));
                        v1 = rn_tf32(0.5f * v1 * (1.0f + erff(v1 * 0.70710678f)));
                    }
                    *(float2*)(C + (size_t)r * N + col) = make_float2(v0, v1);
                }
            }
        }
    }
}

// ---------------- Flash attention (fp32, tf32-rounded ctx output) ----------------
__global__ __launch_bounds__(256)
void attn_kernel(const float* __restrict__ q, const float* __restrict__ k,
                 const float* __restrict__ v, float* __restrict__ ctx) {
    __shared__ __align__(16) float Qt [64][64];
    __shared__ __align__(16) float KtP[64][64];
    __shared__ __align__(16) float Vs [64][64];

    int bh = blockIdx.y;
    int b = bh / HEADS, h = bh % HEADS;
    int q0 = blockIdx.x * 64;
    int tid = threadIdx.x;
    int rg = tid >> 4, kg = tid & 15;
    int r0 = rg * 4, c0 = kg * 4;
    size_t base = (size_t)b * SEQ * DMODEL + h * DH;

    {
        int c = tid >> 2, el = tid & 3;
        int s = q0 + c;
        const float* qp = q + base + (size_t)s * DMODEL;
#pragma unroll
        for (int jj = 0; jj < 4; jj++) {
            int e0 = el * 4 + jj * 16;
            float4 vv = (s < SEQ) ? *(const float4*)(qp + e0) : make_float4(0.f, 0.f, 0.f, 0.f);
            Qt[e0 + 0][c] = vv.x; Qt[e0 + 1][c] = vv.y;
            Qt[e0 + 2][c] = vv.z; Qt[e0 + 3][c] = vv.w;
        }
    }

    float m[4], l[4], O[4][4];
#pragma unroll
    for (int i = 0; i < 4; i++) {
        m[i] = -1e30f; l[i] = 0.f;
#pragma unroll
        for (int j = 0; j < 4; j++) O[i][j] = 0.f;
    }

    const int NT = (SEQ + 63) / 64;
    for (int kt = 0; kt < NT; kt++) {
        int kbase = kt * 64;
        __syncthreads();
        {
            int c = tid >> 2, el = tid & 3;
            int s = kbase + c;
            const float* kp = k + base + (size_t)s * DMODEL;
            const float* vp = v + base + (size_t)s * DMODEL;
#pragma unroll
            for (int jj = 0; jj < 4; jj++) {
                int e0 = el * 4 + jj * 16;
                float4 kv = (s < SEQ) ? *(const float4*)(kp + e0) : make_float4(0.f, 0.f, 0.f, 0.f);
                KtP[e0 + 0][c] = kv.x; KtP[e0 + 1][c] = kv.y;
                KtP[e0 + 2][c] = kv.z; KtP[e0 + 3][c] = kv.w;
                float4 vv = (s < SEQ) ? *(const float4*)(vp + e0) : make_float4(0.f, 0.f, 0.f, 0.f);
                *(float4*)&Vs[c][e0] = vv;
            }
        }
        __syncthreads();

        float sc[4][4];
#pragma unroll
        for (int i = 0; i < 4; i++)
#pragma unroll
            for (int j = 0; j < 4; j++) sc[i][j] = 0.f;
#pragma unroll 8
        for (int d = 0; d < 64; d++) {
            float4 qv = *(const float4*)&Qt[d][r0];
            float4 kv = *(const float4*)&KtP[d][c0];
            float qa[4] = {qv.x, qv.y, qv.z, qv.w};
            float ka[4] = {kv.x, kv.y, kv.z, kv.w};
#pragma unroll
            for (int i = 0; i < 4; i++)
#pragma unroll
                for (int j = 0; j < 4; j++)
                    sc[i][j] += qa[i] * ka[j];
        }
#pragma unroll
        for (int j = 0; j < 4; j++) {
            bool valid = (kbase + c0 + j) < SEQ;
#pragma unroll
            for (int i = 0; i < 4; i++)
                sc[i][j] = valid ? sc[i][j] * 0.125f : -1e30f;
        }
#pragma unroll
        for (int i = 0; i < 4; i++) {
            float mx = sc[i][0];
#pragma unroll
            for (int j = 1; j < 4; j++) mx = fmaxf(mx, sc[i][j]);
#pragma unroll
            for (int o = 1; o < 16; o <<= 1) mx = fmaxf(mx, __shfl_xor_sync(~0u, mx, o));
            float mn = fmaxf(m[i], mx);
            float corr = __expf(m[i] - mn);
            m[i] = mn;
            float ls = 0.f;
#pragma unroll
            for (int j = 0; j < 4; j++) {
                sc[i][j] = __expf(sc[i][j] - mn);
                ls += sc[i][j];
            }
#pragma unroll
            for (int o = 1; o < 16; o <<= 1) ls += __shfl_xor_sync(~0u, ls, o);
            l[i] = l[i] * corr + ls;
#pragma unroll
            for (int j = 0; j < 4; j++) O[i][j] *= corr;
        }
        __syncthreads();
#pragma unroll
        for (int j = 0; j < 4; j++)
#pragma unroll
            for (int i = 0; i < 4; i++)
                KtP[c0 + j][r0 + i] = sc[i][j];
        __syncthreads();
#pragma unroll 8
        for (int c = 0; c < 64; c++) {
            float4 pv = *(const float4*)&KtP[c][r0];
            float4 vv = *(const float4*)&Vs[c][c0];
            float pa[4] = {pv.x, pv.y, pv.z, pv.w};
            float va[4] = {vv.x, vv.y, vv.z, vv.w};
#pragma unroll
            for (int i = 0; i < 4; i++)
#pragma unroll
                for (int j = 0; j < 4; j++)
                    O[i][j] += pa[i] * va[j];
        }
    }

#pragma unroll
    for (int i = 0; i < 4; i++) {
        int s = q0 + r0 + i;
        if (s < SEQ) {
            float inv = 1.0f / l[i];
            float4 o4 = make_float4(rn_tf32(O[i][0] * inv), rn_tf32(O[i][1] * inv),
                                    rn_tf32(O[i][2] * inv), rn_tf32(O[i][3] * inv));
            *(float4*)(ctx + base + (size_t)s * DMODEL + c0) = o4;
        }
    }
}

// ---------------- launch ----------------
extern "C" void kernel_launch(void* const* d_in, const int* in_sizes, int n_in,
                              void* d_out, int out_size) {
    const float* x    = (const float*)d_in[0];
    const float* ln1w = (const float*)d_in[1];
    const float* ln1b = (const float*)d_in[2];
    const float* Wq   = (const float*)d_in[3];
    const float* bq   = (const float*)d_in[4];
    const float* Wk   = (const float*)d_in[5];
    const float* bk   = (const float*)d_in[6];
    const float* Wv   = (const float*)d_in[7];
    const float* bv   = (const float*)d_in[8];
    const float* Wo   = (const float*)d_in[9];
    const float* bo   = (const float*)d_in[10];
    const float* ln2w = (const float*)d_in[11];
    const float* ln2b = (const float*)d_in[12];
    const float* W1   = (const float*)d_in[13];
    const float* b1   = (const float*)d_in[14];
    const float* W2   = (const float*)d_in[15];
    const float* b2   = (const float*)d_in[16];
    float* out = (float*)d_out;

    static float* s_big = nullptr;
    static float* s_h   = nullptr;
    static float* s_wt  = nullptr;
    if (!s_big) {
        cudaGetSymbolAddress((void**)&s_big, g_big);
        cudaGetSymbolAddress((void**)&s_h,   g_h);
        cudaGetSymbolAddress((void**)&s_wt,  g_wt);
        cudaFuncSetAttribute(mma_gemm<0>, cudaFuncAttributeMaxDynamicSharedMemorySize, GEMM_SMEM);
        cudaFuncSetAttribute(mma_gemm<1>, cudaFuncAttributeMaxDynamicSharedMemorySize, GEMM_SMEM);
        cudaFuncSetAttribute(mma_gemm<2>, cudaFuncAttributeMaxDynamicSharedMemorySize, GEMM_SMEM);
    }
    const size_t TD = (size_t)TOK * DMODEL;
    float* h  = s_h;
    float* qb = s_big;
    float* kb = s_big + TD;
    float* vb = s_big + 2 * TD;
    float* cb = s_big + 3 * TD;
    float* fb = s_big;                 // phase B (after cb dead)

    float* WqT = s_wt;                           // [768][768]
    float* WkT = s_wt + 589824;
    float* WvT = s_wt + 2 * 589824;
    float* WoT = s_wt + 3 * 589824;
    float* W1T = s_wt + 4 * 589824;              // [3072][768]
    float* W2T = s_wt + 4 * 589824 + 2359296;    // [768][3072]

    dim3 tb(32, 8);
    transpose_wh<<<dim3(768 / 32, 768 / 32), tb>>>(Wq, WqT, DMODEL);
    transpose_wh<<<dim3(768 / 32, 768 / 32), tb>>>(Wk, WkT, DMODEL);
    transpose_wh<<<dim3(768 / 32, 768 / 32), tb>>>(Wv, WvT, DMODEL);
    transpose_w <<<dim3(768 / 32, 768 / 32), tb>>>(Wo, WoT, DMODEL, DMODEL);
    transpose_w <<<dim3(FFDIM / 32, 768 / 32), tb>>>(W1, W1T, DMODEL, FFDIM);
    transpose_w <<<dim3(768 / 32, FFDIM / 32), tb>>>(W2, W2T, FFDIM, DMODEL);

    dim3 gD(DMODEL / 128, (TOK + 127) / 128);
    dim3 gF(FFDIM  / 128, (TOK + 127) / 128);

    ln_kernel<<<TOK, 256>>>(x, ln1w, ln1b, h);
    mma_gemm<0><<<gD, 256, GEMM_SMEM>>>(h, WqT, bq, nullptr, qb, TOK, DMODEL, DMODEL);
    mma_gemm<0><<<gD, 256, GEMM_SMEM>>>(h, WkT, bk, nullptr, kb, TOK, DMODEL, DMODEL);
    mma_gemm<0><<<gD, 256, GEMM_SMEM>>>(h, WvT, bv, nullptr, vb, TOK, DMODEL, DMODEL);
    attn_kernel<<<dim3((SEQ + 63) / 64, BATCH * HEADS), 256>>>(qb, kb, vb, cb);
    mma_gemm<1><<<gD, 256, GEMM_SMEM>>>(cb, WoT, bo, x, out, TOK, DMODEL, DMODEL);
    ln_kernel<<<TOK, 256>>>(out, ln2w, ln2b, h);
    mma_gemm<2><<<gF, 256, GEMM_SMEM>>>(h, W1T, b1, nullptr, fb, TOK, FFDIM, DMODEL);
    mma_gemm<1><<<gD, 256, GEMM_SMEM>>>(fb, W2T, b2, out, out, TOK, DMODEL, FFDIM);
}

// round 9
// speedup vs baseline: 1.9439x; 1.0201x over previous
#include <cuda_runtime.h>
#include <math.h>
#include <stdint.h>

#define TOK    18464         // B*S = 32*577
#define DMODEL 768
#define HEADS  12
#define DH     64
#define SEQ    577
#define BATCH  32
#define FFDIM  3072
#define NQKV   2304          // 3*DMODEL fused QKV output width

// ---------------- static scratch (no allocations allowed) ----------------
// g_big overlay: phase A [qkv (TOK*2304) | ctx (TOK*768)] ; phase B [ffn TOK*3072]
__device__ float g_big[(size_t)TOK * FFDIM];
__device__ float g_h  [(size_t)TOK * DMODEL];
// WqkvT [2304][768], WoT [768][768], W1T [3072][768], W2T [768][3072]
__device__ float g_wt [2304 * 768 + 768 * 768 + 3072 * 768 + 768 * 3072];
__device__ float g_bias[NQKV];

// ---------------- helpers ----------------
__device__ __forceinline__ uint32_t smem_u32(const void* p) {
    uint32_t a;
    asm("{ .reg .u64 t; cvta.to.shared.u64 t, %1; cvt.u32.u64 %0, t; }" : "=r"(a) : "l"(p));
    return a;
}
__device__ __forceinline__ float rn_tf32(float x) {
    uint32_t u;
    asm("cvt.rna.tf32.f32 %0, %1;" : "=r"(u) : "f"(x));
    return __uint_as_float(u);
}
__device__ __forceinline__ void cp16(uint32_t dst, const void* src, int sz) {
    asm volatile("cp.async.cg.shared.global [%0], [%1], 16, %2;"
                 :: "r"(dst), "l"(src), "r"(sz) : "memory");
}
__device__ __forceinline__ void cp_commit() {
    asm volatile("cp.async.commit_group;" ::: "memory");
}
template<int N>
__device__ __forceinline__ void cp_wait() {
    asm volatile("cp.async.wait_group %0;" :: "n"(N) : "memory");
}
__device__ __forceinline__ void mma_tf32(float* d, const float* a, const float* b) {
    asm volatile(
        "mma.sync.aligned.m16n8k8.row.col.f32.tf32.tf32.f32 "
        "{%0,%1,%2,%3}, {%4,%5,%6,%7}, {%8,%9}, {%0,%1,%2,%3};"
        : "+f"(d[0]), "+f"(d[1]), "+f"(d[2]), "+f"(d[3])
        : "r"(__float_as_uint(a[0])), "r"(__float_as_uint(a[1])),
          "r"(__float_as_uint(a[2])), "r"(__float_as_uint(a[3])),
          "r"(__float_as_uint(b[0])), "r"(__float_as_uint(b[1])));
}

// ---------------- LayerNorm (tf32-rounded output) ----------------
__global__ void ln_kernel(const float* __restrict__ x, const float* __restrict__ w,
                          const float* __restrict__ b, float* __restrict__ out) {
    int t = blockIdx.x;
    const float* xr = x + (size_t)t * DMODEL;
    float* orow = out + (size_t)t * DMODEL;
    float v[3];
    float s = 0.f, ss = 0.f;
#pragma unroll
    for (int i = 0; i < 3; i++) {
        v[i] = xr[threadIdx.x + i * 256];
        s += v[i]; ss += v[i] * v[i];
    }
    __shared__ float red[16];
#pragma unroll
    for (int o = 16; o; o >>= 1) {
        s  += __shfl_xor_sync(~0u, s,  o);
        ss += __shfl_xor_sync(~0u, ss, o);
    }
    int wid = threadIdx.x >> 5, lid = threadIdx.x & 31;
    if (lid == 0) { red[wid] = s; red[8 + wid] = ss; }
    __syncthreads();
    s = 0.f; ss = 0.f;
#pragma unroll
    for (int i = 0; i < 8; i++) { s += red[i]; ss += red[8 + i]; }
    float mean = s * (1.0f / DMODEL);
    float var  = ss * (1.0f / DMODEL) - mean * mean;
    float rstd = rsqrtf(var + 1e-5f);
#pragma unroll
    for (int i = 0; i < 3; i++) {
        int d = threadIdx.x + i * 256;
        orow[d] = rn_tf32((v[i] - mean) * rstd * w[d] + b[d]);
    }
}

// ---------------- fused QKV transpose: (H,768,64)x3 -> WqkvT[2304][768] + bias ----------------
__global__ void transpose_qkv(const float* __restrict__ Wq, const float* __restrict__ Wk,
                              const float* __restrict__ Wv,
                              const float* __restrict__ bq, const float* __restrict__ bk,
                              const float* __restrict__ bv,
                              float* __restrict__ WT, float* __restrict__ bias) {
    __shared__ float t[32][33];
    int n0 = blockIdx.x * 32, k0 = blockIdx.y * 32;
    int n = n0 + threadIdx.x;
    int proj = n / DMODEL;                  // uniform per block (768 % 32 == 0)
    int c = n - proj * DMODEL;
    const float* W = (proj == 0) ? Wq : (proj == 1) ? Wk : Wv;
    const float* Wp = W + (size_t)(c >> 6) * DMODEL * 64 + (c & 63);
#pragma unroll
    for (int j = 0; j < 4; j++)
        t[threadIdx.y + 8 * j][threadIdx.x] = Wp[(size_t)(k0 + threadIdx.y + 8 * j) * 64];
    if (blockIdx.y == 0 && threadIdx.y == 0) {
        const float* bb = (proj == 0) ? bq : (proj == 1) ? bk : bv;
        bias[n] = bb[c];
    }
    __syncthreads();
#pragma unroll
    for (int j = 0; j < 4; j++)
        WT[(size_t)(n0 + threadIdx.y + 8 * j) * DMODEL + k0 + threadIdx.x] =
            rn_tf32(t[threadIdx.x][threadIdx.y + 8 * j]);
}

// ---------------- Wo/W1/W2 transpose in one launch (z dispatch) ----------------
__global__ void transpose_w3(const float* __restrict__ Wo, const float* __restrict__ W1,
                             const float* __restrict__ W2,
                             float* __restrict__ WoT, float* __restrict__ W1T,
                             float* __restrict__ W2T) {
    int z = blockIdx.z;
    const float* W; float* WT; int K, N;
    if (z == 0)      { W = Wo; WT = WoT; K = 768;  N = 768;  }
    else if (z == 1) { W = W1; WT = W1T; K = 768;  N = 3072; }
    else             { W = W2; WT = W2T; K = 3072; N = 768;  }
    int n0 = blockIdx.x * 32, k0 = blockIdx.y * 32;
    if (n0 >= N || k0 >= K) return;
    __shared__ float t[32][33];
#pragma unroll
    for (int j = 0; j < 4; j++)
        t[threadIdx.y + 8 * j][threadIdx.x] =
            W[(size_t)(k0 + threadIdx.y + 8 * j) * N + n0 + threadIdx.x];
    __syncthreads();
#pragma unroll
    for (int j = 0; j < 4; j++)
        WT[(size_t)(n0 + threadIdx.y + 8 * j) * K + k0 + threadIdx.x] =
            rn_tf32(t[threadIdx.x][threadIdx.y + 8 * j]);
}

// ---------------- TF32 warp-MMA GEMM: C[M,N] = A[M,K] @ Bt[N,K]^T ----------------
// Tile 128x128x32, 8 warps (2x4), warp tile 64x32 = 4x4 m16n8k8.
// 3-stage cp.async pipeline, ONE __syncthreads per K-chunk.
// EPI: 0 = +bias ; 1 = +bias+resid ; 2 = gelu(+bias), tf32-rounded
#define STAGE_B 36864u            // (128+128) rows * 36 floats * 4B
#define GEMM_SMEM (3 * 36864)     // 110592

template<int EPI>
__global__ __launch_bounds__(256, 2)
void mma_gemm(const float* __restrict__ A, const float* __restrict__ Bt,
              const float* __restrict__ bias, const float* __restrict__ resid,
              float* __restrict__ C, int M, int N, int K) {
    extern __shared__ float sm[];
    uint32_t sb = smem_u32(sm);
    int tid = threadIdx.x;
    int wid = tid >> 5, lane = tid & 31;
    int g = lane >> 2, t4 = lane & 3;
    int wm = wid >> 2, wn = wid & 3;
    int m0 = blockIdx.y * 128, n0 = blockIdx.x * 128;

    // global->smem mapping: 2 threads per row, 16 floats each
    int lrow = tid >> 1;
    int lcol = (tid & 1) * 16;
    bool aok = (m0 + lrow) < M;
    const float* Aptr = aok ? (A + (size_t)(m0 + lrow) * K + lcol) : A;
    const float* Bptr = Bt + (size_t)(n0 + lrow) * K + lcol;
    int asz = aok ? 16 : 0;
    uint32_t sa = sb + (uint32_t)(lrow * 36 + lcol) * 4;
    uint32_t sbB = sa + 18432;

    float acc[4][4][4];
#pragma unroll
    for (int mi = 0; mi < 4; mi++)
#pragma unroll
        for (int ni = 0; ni < 4; ni++)
#pragma unroll
            for (int j = 0; j < 4; j++) acc[mi][ni][j] = 0.f;

    const int nch = K / 32;

    // prologue: prefetch chunks 0,1 into stages 0,1
#pragma unroll
    for (int p = 0; p < 2; p++) {
        uint32_t off = p * STAGE_B;
#pragma unroll
        for (int q = 0; q < 4; q++) {
            cp16(sa  + off + q * 16, Aptr + p * 32 + q * 4, asz);
            cp16(sbB + off + q * 16, Bptr + p * 32 + q * 4, 16);
        }
        cp_commit();
    }

    int stage = 0;
    for (int i = 0; i < nch; i++) {
        if (i == nch - 1) cp_wait<0>(); else cp_wait<1>();
        __syncthreads();
        if (i + 2 < nch) {
            int ps = (stage + 2 >= 3) ? stage - 1 : stage + 2;   // (stage+2)%3
            uint32_t off = (uint32_t)ps * STAGE_B;
#pragma unroll
            for (int q = 0; q < 4; q++) {
                cp16(sa  + off + q * 16, Aptr + (i + 2) * 32 + q * 4, asz);
                cp16(sbB + off + q * 16, Bptr + (i + 2) * 32 + q * 4, 16);
            }
            cp_commit();
        }

        const float* As = sm + stage * 9216;
        const float* Bs = As + 4608;
#pragma unroll
        for (int kk = 0; kk < 4; kk++) {
            float af[4][4], bf[4][2];
#pragma unroll
            for (int mi = 0; mi < 4; mi++) {
                int r = wm * 64 + mi * 16 + g;
                af[mi][0] = As[r * 36 + kk * 8 + t4];
                af[mi][1] = As[(r + 8) * 36 + kk * 8 + t4];
                af[mi][2] = As[r * 36 + kk * 8 + t4 + 4];
                af[mi][3] = As[(r + 8) * 36 + kk * 8 + t4 + 4];
            }
#pragma unroll
            for (int ni = 0; ni < 4; ni++) {
                int c = wn * 32 + ni * 8 + g;
                bf[ni][0] = Bs[c * 36 + kk * 8 + t4];
                bf[ni][1] = Bs[c * 36 + kk * 8 + t4 + 4];
            }
#pragma unroll
            for (int mi = 0; mi < 4; mi++)
#pragma unroll
                for (int ni = 0; ni < 4; ni++)
                    mma_tf32(acc[mi][ni], af[mi], bf[ni]);
        }
        stage = (stage + 1 == 3) ? 0 : stage + 1;
    }

    // epilogue
#pragma unroll
    for (int mi = 0; mi < 4; mi++) {
        int r1 = m0 + wm * 64 + mi * 16 + g;
        int r2 = r1 + 8;
#pragma unroll
        for (int ni = 0; ni < 4; ni++) {
            int col = n0 + wn * 32 + ni * 8 + 2 * t4;
            float2 bs = *(const float2*)(bias + col);
#pragma unroll
            for (int hrow = 0; hrow < 2; hrow++) {
                int r = hrow ? r2 : r1;
                if (r < M) {
                    float v0 = acc[mi][ni][hrow * 2 + 0] + bs.x;
                    float v1 = acc[mi][ni][hrow * 2 + 1] + bs.y;
                    if (EPI == 1) {
                        float2 rv = *(const float2*)(resid + (size_t)r * N + col);
                        v0 += rv.x; v1 += rv.y;
                    }
                    if (EPI == 2) {
                        v0 = rn_tf32(0.5f * v0 * (1.0f + erff(v0 * 0.70710678f)));
                        v1 = rn_tf32(0.5f * v1 * (1.0f + erff(v1 * 0.70710678f)));
                    }
                    *(float2*)(C + (size_t)r * N + col) = make_float2(v0, v1);
                }
            }
        }
    }
}

// ---------------- Flash attention over fused qkv [TOK][2304] ----------------
__global__ __launch_bounds__(256)
void attn_kernel(const float* __restrict__ qkv, float* __restrict__ ctx) {
    __shared__ __align__(16) float Qt [64][64];
    __shared__ __align__(16) float KtP[64][64];
    __shared__ __align__(16) float Vs [64][64];

    int bh = blockIdx.y;
    int b = bh / HEADS, h = bh % HEADS;
    int q0 = blockIdx.x * 64;
    int tid = threadIdx.x;
    int rg = tid >> 4, kg = tid & 15;
    int r0 = rg * 4, c0 = kg * 4;
    size_t baseq = (size_t)b * SEQ * NQKV + h * DH;       // q at +0, k at +768, v at +1536
    size_t baseo = (size_t)b * SEQ * DMODEL + h * DH;

    {
        int c = tid >> 2, el = tid & 3;
        int s = q0 + c;
        const float* qp = qkv + baseq + (size_t)s * NQKV;
#pragma unroll
        for (int jj = 0; jj < 4; jj++) {
            int e0 = el * 4 + jj * 16;
            float4 vv = (s < SEQ) ? *(const float4*)(qp + e0) : make_float4(0.f, 0.f, 0.f, 0.f);
            Qt[e0 + 0][c] = vv.x; Qt[e0 + 1][c] = vv.y;
            Qt[e0 + 2][c] = vv.z; Qt[e0 + 3][c] = vv.w;
        }
    }

    float m[4], l[4], O[4][4];
#pragma unroll
    for (int i = 0; i < 4; i++) {
        m[i] = -1e30f; l[i] = 0.f;
#pragma unroll
        for (int j = 0; j < 4; j++) O[i][j] = 0.f;
    }

    const int NT = (SEQ + 63) / 64;
    for (int kt = 0; kt < NT; kt++) {
        int kbase = kt * 64;
        __syncthreads();
        {
            int c = tid >> 2, el = tid & 3;
            int s = kbase + c;
            const float* kp = qkv + baseq + 768  + (size_t)s * NQKV;
            const float* vp = qkv + baseq + 1536 + (size_t)s * NQKV;
#pragma unroll
            for (int jj = 0; jj < 4; jj++) {
                int e0 = el * 4 + jj * 16;
                float4 kv = (s < SEQ) ? *(const float4*)(kp + e0) : make_float4(0.f, 0.f, 0.f, 0.f);
                KtP[e0 + 0][c] = kv.x; KtP[e0 + 1][c] = kv.y;
                KtP[e0 + 2][c] = kv.z; KtP[e0 + 3][c] = kv.w;
                float4 vv = (s < SEQ) ? *(const float4*)(vp + e0) : make_float4(0.f, 0.f, 0.f, 0.f);
                *(float4*)&Vs[c][e0] = vv;
            }
        }
        __syncthreads();

        float sc[4][4];
#pragma unroll
        for (int i = 0; i < 4; i++)
#pragma unroll
            for (int j = 0; j < 4; j++) sc[i][j] = 0.f;
#pragma unroll 8
        for (int d = 0; d < 64; d++) {
            float4 qv = *(const float4*)&Qt[d][r0];
            float4 kv = *(const float4*)&KtP[d][c0];
            float qa[4] = {qv.x, qv.y, qv.z, qv.w};
            float ka[4] = {kv.x, kv.y, kv.z, kv.w};
#pragma unroll
            for (int i = 0; i < 4; i++)
#pragma unroll
                for (int j = 0; j < 4; j++)
                    sc[i][j] += qa[i] * ka[j];
        }
#pragma unroll
        for (int j = 0; j < 4; j++) {
            bool valid = (kbase + c0 + j) < SEQ;
#pragma unroll
            for (int i = 0; i < 4; i++)
                sc[i][j] = valid ? sc[i][j] * 0.125f : -1e30f;
        }
#pragma unroll
        for (int i = 0; i < 4; i++) {
            float mx = sc[i][0];
#pragma unroll
            for (int j = 1; j < 4; j++) mx = fmaxf(mx, sc[i][j]);
#pragma unroll
            for (int o = 1; o < 16; o <<= 1) mx = fmaxf(mx, __shfl_xor_sync(~0u, mx, o));
            float mn = fmaxf(m[i], mx);
            float corr = __expf(m[i] - mn);
            m[i] = mn;
            float ls = 0.f;
#pragma unroll
            for (int j = 0; j < 4; j++) {
                sc[i][j] = __expf(sc[i][j] - mn);
                ls += sc[i][j];
            }
#pragma unroll
            for (int o = 1; o < 16; o <<= 1) ls += __shfl_xor_sync(~0u, ls, o);
            l[i] = l[i] * corr + ls;
#pragma unroll
            for (int j = 0; j < 4; j++) O[i][j] *= corr;
        }
        __syncthreads();
#pragma unroll
        for (int j = 0; j < 4; j++)
#pragma unroll
            for (int i = 0; i < 4; i++)
                KtP[c0 + j][r0 + i] = sc[i][j];
        __syncthreads();
#pragma unroll 8
        for (int c = 0; c < 64; c++) {
            float4 pv = *(const float4*)&KtP[c][r0];
            float4 vv = *(const float4*)&Vs[c][c0];
            float pa[4] = {pv.x, pv.y, pv.z, pv.w};
            float va[4] = {vv.x, vv.y, vv.z, vv.w};
#pragma unroll
            for (int i = 0; i < 4; i++)
#pragma unroll
                for (int j = 0; j < 4; j++)
                    O[i][j] += pa[i] * va[j];
        }
    }

#pragma unroll
    for (int i = 0; i < 4; i++) {
        int s = q0 + r0 + i;
        if (s < SEQ) {
            float inv = 1.0f / l[i];
            float4 o4 = make_float4(rn_tf32(O[i][0] * inv), rn_tf32(O[i][1] * inv),
                                    rn_tf32(O[i][2] * inv), rn_tf32(O[i][3] * inv));
            *(float4*)(ctx + baseo + (size_t)s * DMODEL + c0) = o4;
        }
    }
}

// ---------------- launch ----------------
extern "C" void kernel_launch(void* const* d_in, const int* in_sizes, int n_in,
                              void* d_out, int out_size) {
    const float* x    = (const float*)d_in[0];
    const float* ln1w = (const float*)d_in[1];
    const float* ln1b = (const float*)d_in[2];
    const float* Wq   = (const float*)d_in[3];
    const float* bq   = (const float*)d_in[4];
    const float* Wk   = (const float*)d_in[5];
    const float* bk   = (const float*)d_in[6];
    const float* Wv   = (const float*)d_in[7];
    const float* bv   = (const float*)d_in[8];
    const float* Wo   = (const float*)d_in[9];
    const float* bo   = (const float*)d_in[10];
    const float* ln2w = (const float*)d_in[11];
    const float* ln2b = (const float*)d_in[12];
    const float* W1   = (const float*)d_in[13];
    const float* b1   = (const float*)d_in[14];
    const float* W2   = (const float*)d_in[15];
    const float* b2   = (const float*)d_in[16];
    float* out = (float*)d_out;

    static float* s_big = nullptr;
    static float* s_h   = nullptr;
    static float* s_wt  = nullptr;
    static float* s_bias = nullptr;
    if (!s_big) {
        cudaGetSymbolAddress((void**)&s_big, g_big);
        cudaGetSymbolAddress((void**)&s_h,   g_h);
        cudaGetSymbolAddress((void**)&s_wt,  g_wt);
        cudaGetSymbolAddress((void**)&s_bias, g_bias);
        cudaFuncSetAttribute(mma_gemm<0>, cudaFuncAttributeMaxDynamicSharedMemorySize, GEMM_SMEM);
        cudaFuncSetAttribute(mma_gemm<1>, cudaFuncAttributeMaxDynamicSharedMemorySize, GEMM_SMEM);
        cudaFuncSetAttribute(mma_gemm<2>, cudaFuncAttributeMaxDynamicSharedMemorySize, GEMM_SMEM);
    }
    const size_t TD = (size_t)TOK * DMODEL;
    float* h   = s_h;
    float* qkv = s_big;                 // [TOK][2304]
    float* cb  = s_big + 3 * TD;        // ctx [TOK][768]
    float* fb  = s_big;                 // phase B ffn [TOK][3072]

    float* WqkvT = s_wt;                                   // [2304][768]
    float* WoT   = s_wt + 2304 * 768;                      // [768][768]
    float* W1T   = WoT + 768 * 768;                        // [3072][768]
    float* W2T   = W1T + 3072 * 768;                       // [768][3072]

    dim3 tb(32, 8);
    // launch 0
    transpose_qkv<<<dim3(NQKV / 32, DMODEL / 32), tb>>>(Wq, Wk, Wv, bq, bk, bv, WqkvT, s_bias);
    // launch 1
    transpose_w3<<<dim3(96, 96, 3), tb>>>(Wo, W1, W2, WoT, W1T, W2T);

    dim3 gQKV(NQKV / 128, (TOK + 127) / 128);
    dim3 gD(DMODEL / 128, (TOK + 127) / 128);
    dim3 gF(FFDIM / 128, (TOK + 127) / 128);

    // launch 2
    ln_kernel<<<TOK, 256>>>(x, ln1w, ln1b, h);
    // launch 3: fused QKV
    mma_gemm<0><<<gQKV, 256, GEMM_SMEM>>>(h, WqkvT, s_bias, nullptr, qkv, TOK, NQKV, DMODEL);
    // launch 4
    attn_kernel<<<dim3((SEQ + 63) / 64, BATCH * HEADS), 256>>>(qkv, cb);
    // launch 5 (ncu -s 5 profiles this): Wo GEMM + residual
    mma_gemm<1><<<gD, 256, GEMM_SMEM>>>(cb, WoT, bo, x, out, TOK, DMODEL, DMODEL);
    // launch 6
    ln_kernel<<<TOK, 256>>>(out, ln2w, ln2b, h);
    // launch 7: MLP up + GELU
    mma_gemm<2><<<gF, 256, GEMM_SMEM>>>(h, W1T, b1, nullptr, fb, TOK, FFDIM, DMODEL);
    // launch 8: MLP down + residual
    mma_gemm<1><<<gD, 256, GEMM_SMEM>>>(fb, W2T, b2, out, out, TOK, DMODEL, FFDIM);
}

// round 11
// speedup vs baseline: 2.3134x; 1.1901x over previous
#include <cuda_runtime.h>
#include <math.h>
#include <stdint.h>

#define TOK    18464         // B*S = 32*577
#define DMODEL 768
#define HEADS  12
#define DH     64
#define SEQ    577
#define BATCH  32
#define FFDIM  3072
#define NQKV   2304          // 3*DMODEL fused QKV output width

// ---------------- static scratch (no allocations allowed) ----------------
// g_big overlay: phase A [qkv (TOK*2304) | ctx (TOK*768)] ; phase B [ffn TOK*3072]
__device__ float g_big[(size_t)TOK * FFDIM];
__device__ float g_h  [(size_t)TOK * DMODEL];
// WqkvT [2304][768], WoT [768][768], W1T [3072][768], W2T [768][3072]
__device__ float g_wt [2304 * 768 + 768 * 768 + 3072 * 768 + 768 * 3072];
__device__ float g_bias[NQKV];

// ---------------- helpers ----------------
__device__ __forceinline__ uint32_t smem_u32(const void* p) {
    uint32_t a;
    asm("{ .reg .u64 t; cvta.to.shared.u64 t, %1; cvt.u32.u64 %0, t; }" : "=r"(a) : "l"(p));
    return a;
}
__device__ __forceinline__ float rn_tf32(float x) {
    uint32_t u;
    asm("cvt.rna.tf32.f32 %0, %1;" : "=r"(u) : "f"(x));
    return __uint_as_float(u);
}
__device__ __forceinline__ void cp16(uint32_t dst, const void* src, int sz) {
    asm volatile("cp.async.cg.shared.global [%0], [%1], 16, %2;"
                 :: "r"(dst), "l"(src), "r"(sz) : "memory");
}
__device__ __forceinline__ void cp_commit() {
    asm volatile("cp.async.commit_group;" ::: "memory");
}
template<int N>
__device__ __forceinline__ void cp_wait() {
    asm volatile("cp.async.wait_group %0;" :: "n"(N) : "memory");
}
__device__ __forceinline__ void mma_tf32(float* d, const float* a, const float* b) {
    asm volatile(
        "mma.sync.aligned.m16n8k8.row.col.f32.tf32.tf32.f32 "
        "{%0,%1,%2,%3}, {%4,%5,%6,%7}, {%8,%9}, {%0,%1,%2,%3};"
        : "+f"(d[0]), "+f"(d[1]), "+f"(d[2]), "+f"(d[3])
        : "r"(__float_as_uint(a[0])), "r"(__float_as_uint(a[1])),
          "r"(__float_as_uint(a[2])), "r"(__float_as_uint(a[3])),
          "r"(__float_as_uint(b[0])), "r"(__float_as_uint(b[1])));
}

// ---------------- LayerNorm (tf32-rounded output) ----------------
__global__ void ln_kernel(const float* __restrict__ x, const float* __restrict__ w,
                          const float* __restrict__ b, float* __restrict__ out) {
    int t = blockIdx.x;
    const float* xr = x + (size_t)t * DMODEL;
    float* orow = out + (size_t)t * DMODEL;
    float v[3];
    float s = 0.f, ss = 0.f;
#pragma unroll
    for (int i = 0; i < 3; i++) {
        v[i] = xr[threadIdx.x + i * 256];
        s += v[i]; ss += v[i] * v[i];
    }
    __shared__ float red[16];
#pragma unroll
    for (int o = 16; o; o >>= 1) {
        s  += __shfl_xor_sync(~0u, s,  o);
        ss += __shfl_xor_sync(~0u, ss, o);
    }
    int wid = threadIdx.x >> 5, lid = threadIdx.x & 31;
    if (lid == 0) { red[wid] = s; red[8 + wid] = ss; }
    __syncthreads();
    s = 0.f; ss = 0.f;
#pragma unroll
    for (int i = 0; i < 8; i++) { s += red[i]; ss += red[8 + i]; }
    float mean = s * (1.0f / DMODEL);
    float var  = ss * (1.0f / DMODEL) - mean * mean;
    float rstd = rsqrtf(var + 1e-5f);
#pragma unroll
    for (int i = 0; i < 3; i++) {
        int d = threadIdx.x + i * 256;
        orow[d] = rn_tf32((v[i] - mean) * rstd * w[d] + b[d]);
    }
}

// ---------------- fused QKV transpose: (H,768,64)x3 -> WqkvT[2304][768] + bias ----------------
__global__ void transpose_qkv(const float* __restrict__ Wq, const float* __restrict__ Wk,
                              const float* __restrict__ Wv,
                              const float* __restrict__ bq, const float* __restrict__ bk,
                              const float* __restrict__ bv,
                              float* __restrict__ WT, float* __restrict__ bias) {
    __shared__ float t[32][33];
    int n0 = blockIdx.x * 32, k0 = blockIdx.y * 32;
    int n = n0 + threadIdx.x;
    int proj = n / DMODEL;                  // uniform per block (768 % 32 == 0)
    int c = n - proj * DMODEL;
    const float* W = (proj == 0) ? Wq : (proj == 1) ? Wk : Wv;
    const float* Wp = W + (size_t)(c >> 6) * DMODEL * 64 + (c & 63);
#pragma unroll
    for (int j = 0; j < 4; j++)
        t[threadIdx.y + 8 * j][threadIdx.x] = Wp[(size_t)(k0 + threadIdx.y + 8 * j) * 64];
    if (blockIdx.y == 0 && threadIdx.y == 0) {
        const float* bb = (proj == 0) ? bq : (proj == 1) ? bk : bv;
        bias[n] = bb[c];
    }
    __syncthreads();
#pragma unroll
    for (int j = 0; j < 4; j++)
        WT[(size_t)(n0 + threadIdx.y + 8 * j) * DMODEL + k0 + threadIdx.x] =
            rn_tf32(t[threadIdx.x][threadIdx.y + 8 * j]);
}

// ---------------- Wo/W1/W2 transpose in one launch (z dispatch) ----------------
__global__ void transpose_w3(const float* __restrict__ Wo, const float* __restrict__ W1,
                             const float* __restrict__ W2,
                             float* __restrict__ WoT, float* __restrict__ W1T,
                             float* __restrict__ W2T) {
    int z = blockIdx.z;
    const float* W; float* WT; int K, N;
    if (z == 0)      { W = Wo; WT = WoT; K = 768;  N = 768;  }
    else if (z == 1) { W = W1; WT = W1T; K = 768;  N = 3072; }
    else             { W = W2; WT = W2T; K = 3072; N = 768;  }
    int n0 = blockIdx.x * 32, k0 = blockIdx.y * 32;
    if (n0 >= N || k0 >= K) return;
    __shared__ float t[32][33];
#pragma unroll
    for (int j = 0; j < 4; j++)
        t[threadIdx.y + 8 * j][threadIdx.x] =
            W[(size_t)(k0 + threadIdx.y + 8 * j) * N + n0 + threadIdx.x];
    __syncthreads();
#pragma unroll
    for (int j = 0; j < 4; j++)
        WT[(size_t)(n0 + threadIdx.y + 8 * j) * K + k0 + threadIdx.x] =
            rn_tf32(t[threadIdx.x][threadIdx.y + 8 * j]);
}

// ---------------- TF32 warp-MMA GEMM: C[M,N] = A[M,K] @ Bt[N,K]^T ----------------
// Tile 128x128x32, 8 warps (2x4), warp tile 64x32 = 4x4 m16n8k8.
// 3-stage cp.async pipeline, ONE __syncthreads per K-chunk.
// Fragment loads use k-slot relabeling (slot t4 <-> phys 2*t4, slot t4+4 <-> 2*t4+1),
// valid because A and B use the SAME permutation -> float2 LDS.
// EPI: 0 = +bias ; 1 = +bias+resid ; 2 = gelu(+bias), tf32-rounded
#define STAGE_B 36864u            // (128+128) rows * 36 floats * 4B
#define GEMM_SMEM (3 * 36864)     // 110592

template<int EPI>
__global__ __launch_bounds__(256, 2)
void mma_gemm(const float* __restrict__ A, const float* __restrict__ Bt,
              const float* __restrict__ bias, const float* __restrict__ resid,
              float* __restrict__ C, int M, int N, int K) {
    extern __shared__ float sm[];
    uint32_t sb = smem_u32(sm);
    int tid = threadIdx.x;
    int wid = tid >> 5, lane = tid & 31;
    int g = lane >> 2, t4 = lane & 3;
    int wm = wid >> 2, wn = wid & 3;
    int m0 = blockIdx.y * 128, n0 = blockIdx.x * 128;

    int lrow = tid >> 1;
    int lcol = (tid & 1) * 16;
    bool aok = (m0 + lrow) < M;
    const float* Aptr = aok ? (A + (size_t)(m0 + lrow) * K + lcol) : A;
    const float* Bptr = Bt + (size_t)(n0 + lrow) * K + lcol;
    int asz = aok ? 16 : 0;
    uint32_t sa = sb + (uint32_t)(lrow * 36 + lcol) * 4;
    uint32_t sbB = sa + 18432;

    float acc[4][4][4];
#pragma unroll
    for (int mi = 0; mi < 4; mi++)
#pragma unroll
        for (int ni = 0; ni < 4; ni++)
#pragma unroll
            for (int j = 0; j < 4; j++) acc[mi][ni][j] = 0.f;

    const int nch = K / 32;

#pragma unroll
    for (int p = 0; p < 2; p++) {
        uint32_t off = p * STAGE_B;
#pragma unroll
        for (int q = 0; q < 4; q++) {
            cp16(sa  + off + q * 16, Aptr + p * 32 + q * 4, asz);
            cp16(sbB + off + q * 16, Bptr + p * 32 + q * 4, 16);
        }
        cp_commit();
    }

    int stage = 0;
    for (int i = 0; i < nch; i++) {
        if (i == nch - 1) cp_wait<0>(); else cp_wait<1>();
        __syncthreads();
        if (i + 2 < nch) {
            int ps = (stage + 2 >= 3) ? stage - 1 : stage + 2;   // (stage+2)%3
            uint32_t off = (uint32_t)ps * STAGE_B;
#pragma unroll
            for (int q = 0; q < 4; q++) {
                cp16(sa  + off + q * 16, Aptr + (i + 2) * 32 + q * 4, asz);
                cp16(sbB + off + q * 16, Bptr + (i + 2) * 32 + q * 4, 16);
            }
            cp_commit();
        }

        const float* As = sm + stage * 9216;
        const float* Bs = As + 4608;
#pragma unroll
        for (int kk = 0; kk < 4; kk++) {
            float af[4][4], bf[4][2];
#pragma unroll
            for (int mi = 0; mi < 4; mi++) {
                int r = wm * 64 + mi * 16 + g;
                float2 lo = *(const float2*)&As[r * 36 + kk * 8 + 2 * t4];
                float2 hi = *(const float2*)&As[(r + 8) * 36 + kk * 8 + 2 * t4];
                af[mi][0] = lo.x; af[mi][1] = hi.x; af[mi][2] = lo.y; af[mi][3] = hi.y;
            }
#pragma unroll
            for (int ni = 0; ni < 4; ni++) {
                int c = wn * 32 + ni * 8 + g;
                float2 bb = *(const float2*)&Bs[c * 36 + kk * 8 + 2 * t4];
                bf[ni][0] = bb.x; bf[ni][1] = bb.y;
            }
#pragma unroll
            for (int mi = 0; mi < 4; mi++)
#pragma unroll
                for (int ni = 0; ni < 4; ni++)
                    mma_tf32(acc[mi][ni], af[mi], bf[ni]);
        }
        stage = (stage + 1 == 3) ? 0 : stage + 1;
    }

    // epilogue
#pragma unroll
    for (int mi = 0; mi < 4; mi++) {
        int r1 = m0 + wm * 64 + mi * 16 + g;
        int r2 = r1 + 8;
#pragma unroll
        for (int ni = 0; ni < 4; ni++) {
            int col = n0 + wn * 32 + ni * 8 + 2 * t4;
            float2 bs = *(const float2*)(bias + col);
#pragma unroll
            for (int hrow = 0; hrow < 2; hrow++) {
                int r = hrow ? r2 : r1;
                if (r < M) {
                    float v0 = acc[mi][ni][hrow * 2 + 0] + bs.x;
                    float v1 = acc[mi][ni][hrow * 2 + 1] + bs.y;
                    if (EPI == 1) {
                        float2 rv = *(const float2*)(resid + (size_t)r * N + col);
                        v0 += rv.x; v1 += rv.y;
                    }
                    if (EPI == 2) {
                        v0 = rn_tf32(0.5f * v0 * (1.0f + erff(v0 * 0.70710678f)));
                        v1 = rn_tf32(0.5f * v1 * (1.0f + erff(v1 * 0.70710678f)));
                    }
                    *(float2*)(C + (size_t)r * N + col) = make_float2(v0, v1);
                }
            }
        }
    }
}

// ---------------- MMA flash attention over fused qkv [TOK][2304] ----------------
// Block = 128 q-rows of one (b,h). 8 warps, warp = 16 rows x 64 cols.
// QK^T and PV both m16n8k8 tf32 with rna-prerounded operands.
// S C-fragments feed PV A-fragments directly via the k-slot relabel trick.
#define ATTN_SMEM ((128 * 68 + 64 * 68 + 64 * 68) * 4)   // 69632 B

__global__ __launch_bounds__(256, 2)
void attn_kernel(const float* __restrict__ qkv, float* __restrict__ ctx) {
    extern __shared__ float smf[];
    float* Qs = smf;                   // [128][68]
    float* Ks = smf + 128 * 68;        // [64][68]  row = key, col = d
    float* Vs = Ks + 64 * 68;          // [64][68]  row = key, col = d
    int bh = blockIdx.y;
    int b = bh / HEADS, h = bh % HEADS;
    int q0 = blockIdx.x * 128;
    int tid = threadIdx.x;
    int wid = tid >> 5, lane = tid & 31;
    int g = lane >> 2, t4 = lane & 3;
    size_t baseq = (size_t)b * SEQ * NQKV + h * DH;   // q +0, k +768, v +1536
    size_t baseo = (size_t)b * SEQ * DMODEL + h * DH;

    // load Q tile (rounded)
    {
        int r = tid >> 1;
        int c0 = (tid & 1) * 32;
        int s = q0 + r;
        float* dst = Qs + r * 68 + c0;
        if (s < SEQ) {
            const float* qp = qkv + baseq + (size_t)s * NQKV + c0;
#pragma unroll
            for (int j = 0; j < 8; j++) {
                float4 v = *(const float4*)(qp + j * 4);
                *(float4*)(dst + j * 4) = make_float4(rn_tf32(v.x), rn_tf32(v.y),
                                                      rn_tf32(v.z), rn_tf32(v.w));
            }
        } else {
#pragma unroll
            for (int j = 0; j < 8; j++)
                *(float4*)(dst + j * 4) = make_float4(0.f, 0.f, 0.f, 0.f);
        }
    }

    float mr[2] = {-1e30f, -1e30f};
    float lr[2] = {0.f, 0.f};
    float O[8][4];
#pragma unroll
    for (int nt = 0; nt < 8; nt++)
#pragma unroll
        for (int j = 0; j < 4; j++) O[nt][j] = 0.f;

    int rA = wid * 16 + g;
    const int NT = (SEQ + 63) / 64;   // 10
    for (int kt = 0; kt < NT; kt++) {
        __syncthreads();
        // load K,V tile (rounded)
        {
            int r = tid >> 2;
            int c0 = (tid & 3) * 16;
            int s = kt * 64 + r;
            float* dk = Ks + r * 68 + c0;
            float* dv = Vs + r * 68 + c0;
            if (s < SEQ) {
                const float* kp = qkv + baseq + 768  + (size_t)s * NQKV + c0;
                const float* vp = qkv + baseq + 1536 + (size_t)s * NQKV + c0;
#pragma unroll
                for (int j = 0; j < 4; j++) {
                    float4 kv = *(const float4*)(kp + j * 4);
                    *(float4*)(dk + j * 4) = make_float4(rn_tf32(kv.x), rn_tf32(kv.y),
                                                         rn_tf32(kv.z), rn_tf32(kv.w));
                    float4 vv = *(const float4*)(vp + j * 4);
                    *(float4*)(dv + j * 4) = make_float4(rn_tf32(vv.x), rn_tf32(vv.y),
                                                         rn_tf32(vv.z), rn_tf32(vv.w));
                }
            } else {
#pragma unroll
                for (int j = 0; j < 4; j++) {
                    *(float4*)(dk + j * 4) = make_float4(0.f, 0.f, 0.f, 0.f);
                    *(float4*)(dv + j * 4) = make_float4(0.f, 0.f, 0.f, 0.f);
                }
            }
        }
        __syncthreads();

        // S = Q K^T  (warp: 16 rows x 64 keys)
        float S[8][4];
#pragma unroll
        for (int nt = 0; nt < 8; nt++)
#pragma unroll
            for (int j = 0; j < 4; j++) S[nt][j] = 0.f;
#pragma unroll
        for (int kk = 0; kk < 8; kk++) {
            float2 alo = *(const float2*)&Qs[rA * 68 + kk * 8 + 2 * t4];
            float2 ahi = *(const float2*)&Qs[(rA + 8) * 68 + kk * 8 + 2 * t4];
            float a[4] = {alo.x, ahi.x, alo.y, ahi.y};
#pragma unroll
            for (int nt = 0; nt < 8; nt++) {
                float2 bb = *(const float2*)&Ks[(nt * 8 + g) * 68 + kk * 8 + 2 * t4];
                float bf[2] = {bb.x, bb.y};
                mma_tf32(S[nt], a, bf);
            }
        }

        // scale + mask + online softmax (rows g and g+8 of this warp)
#pragma unroll
        for (int nt = 0; nt < 8; nt++) {
            int c0v = kt * 64 + nt * 8 + 2 * t4;
            bool v0 = c0v < SEQ, v1 = (c0v + 1) < SEQ;
            S[nt][0] = v0 ? S[nt][0] * 0.125f : -1e30f;
            S[nt][1] = v1 ? S[nt][1] * 0.125f : -1e30f;
            S[nt][2] = v0 ? S[nt][2] * 0.125f : -1e30f;
            S[nt][3] = v1 ? S[nt][3] * 0.125f : -1e30f;
        }
        float mx0 = -1e30f, mx1 = -1e30f;
#pragma unroll
        for (int nt = 0; nt < 8; nt++) {
            mx0 = fmaxf(mx0, fmaxf(S[nt][0], S[nt][1]));
            mx1 = fmaxf(mx1, fmaxf(S[nt][2], S[nt][3]));
        }
#pragma unroll
        for (int o = 1; o < 4; o <<= 1) {
            mx0 = fmaxf(mx0, __shfl_xor_sync(~0u, mx0, o));
            mx1 = fmaxf(mx1, __shfl_xor_sync(~0u, mx1, o));
        }
        float mn0 = fmaxf(mr[0], mx0), mn1 = fmaxf(mr[1], mx1);
        float corr0 = __expf(mr[0] - mn0), corr1 = __expf(mr[1] - mn1);
        mr[0] = mn0; mr[1] = mn1;
        float ls0 = 0.f, ls1 = 0.f;
#pragma unroll
        for (int nt = 0; nt < 8; nt++) {
            S[nt][0] = rn_tf32(__expf(S[nt][0] - mn0));
            S[nt][1] = rn_tf32(__expf(S[nt][1] - mn0));
            S[nt][2] = rn_tf32(__expf(S[nt][2] - mn1));
            S[nt][3] = rn_tf32(__expf(S[nt][3] - mn1));
            ls0 += S[nt][0] + S[nt][1];
            ls1 += S[nt][2] + S[nt][3];
        }
#pragma unroll
        for (int o = 1; o < 4; o <<= 1) {
            ls0 += __shfl_xor_sync(~0u, ls0, o);
            ls1 += __shfl_xor_sync(~0u, ls1, o);
        }
        lr[0] = lr[0] * corr0 + ls0;
        lr[1] = lr[1] * corr1 + ls1;
#pragma unroll
        for (int nt = 0; nt < 8; nt++) {
            O[nt][0] *= corr0; O[nt][1] *= corr0;
            O[nt][2] *= corr1; O[nt][3] *= corr1;
        }

        // O += P V : contraction over keys; kk-th key group = S[kk] fragments
#pragma unroll
        for (int kk = 0; kk < 8; kk++) {
            float a[4] = {S[kk][0], S[kk][2], S[kk][1], S[kk][3]};
#pragma unroll
            for (int nt = 0; nt < 8; nt++) {
                float bf[2];
                bf[0] = Vs[(kk * 8 + 2 * t4) * 68 + nt * 8 + g];
                bf[1] = Vs[(kk * 8 + 2 * t4 + 1) * 68 + nt * 8 + g];
                mma_tf32(O[nt], a, bf);
            }
        }
    }

    // write ctx (rounded for the Wo GEMM)
    float inv0 = 1.0f / lr[0], inv1 = 1.0f / lr[1];
    int s0 = q0 + wid * 16 + g;
    int s1 = s0 + 8;
#pragma unroll
    for (int nt = 0; nt < 8; nt++) {
        int col = nt * 8 + 2 * t4;
        if (s0 < SEQ)
            *(float2*)(ctx + baseo + (size_t)s0 * DMODEL + col) =
                make_float2(rn_tf32(O[nt][0] * inv0), rn_tf32(O[nt][1] * inv0));
        if (s1 < SEQ)
            *(float2*)(ctx + baseo + (size_t)s1 * DMODEL + col) =
                make_float2(rn_tf32(O[nt][2] * inv1), rn_tf32(O[nt][3] * inv1));
    }
}

// ---------------- launch ----------------
extern "C" void kernel_launch(void* const* d_in, const int* in_sizes, int n_in,
                              void* d_out, int out_size) {
    const float* x    = (const float*)d_in[0];
    const float* ln1w = (const float*)d_in[1];
    const float* ln1b = (const float*)d_in[2];
    const float* Wq   = (const float*)d_in[3];
    const float* bq   = (const float*)d_in[4];
    const float* Wk   = (const float*)d_in[5];
    const float* bk   = (const float*)d_in[6];
    const float* Wv   = (const float*)d_in[7];
    const float* bv   = (const float*)d_in[8];
    const float* Wo   = (const float*)d_in[9];
    const float* bo   = (const float*)d_in[10];
    const float* ln2w = (const float*)d_in[11];
    const float* ln2b = (const float*)d_in[12];
    const float* W1   = (const float*)d_in[13];
    const float* b1   = (const float*)d_in[14];
    const float* W2   = (const float*)d_in[15];
    const float* b2   = (const float*)d_in[16];
    float* out = (float*)d_out;

    static float* s_big = nullptr;
    static float* s_h   = nullptr;
    static float* s_wt  = nullptr;
    static float* s_bias = nullptr;
    if (!s_big) {
        cudaGetSymbolAddress((void**)&s_big, g_big);
        cudaGetSymbolAddress((void**)&s_h,   g_h);
        cudaGetSymbolAddress((void**)&s_wt,  g_wt);
        cudaGetSymbolAddress((void**)&s_bias, g_bias);
        cudaFuncSetAttribute(mma_gemm<0>, cudaFuncAttributeMaxDynamicSharedMemorySize, GEMM_SMEM);
        cudaFuncSetAttribute(mma_gemm<1>, cudaFuncAttributeMaxDynamicSharedMemorySize, GEMM_SMEM);
        cudaFuncSetAttribute(mma_gemm<2>, cudaFuncAttributeMaxDynamicSharedMemorySize, GEMM_SMEM);
        cudaFuncSetAttribute(attn_kernel, cudaFuncAttributeMaxDynamicSharedMemorySize, ATTN_SMEM);
    }
    const size_t TD = (size_t)TOK * DMODEL;
    float* h   = s_h;
    float* qkv = s_big;                 // [TOK][2304]
    float* cb  = s_big + 3 * TD;        // ctx [TOK][768]
    float* fb  = s_big;                 // phase B ffn [TOK][3072]

    float* WqkvT = s_wt;                                   // [2304][768]
    float* WoT   = s_wt + 2304 * 768;                      // [768][768]
    float* W1T   = WoT + 768 * 768;                        // [3072][768]
    float* W2T   = W1T + 3072 * 768;                       // [768][3072]

    dim3 tb(32, 8);
    dim3 gQKV(NQKV / 128, (TOK + 127) / 128);
    dim3 gD(DMODEL / 128, (TOK + 127) / 128);
    dim3 gF(FFDIM / 128, (TOK + 127) / 128);

    // launch 0
    transpose_qkv<<<dim3(NQKV / 32, DMODEL / 32), tb>>>(Wq, Wk, Wv, bq, bk, bv, WqkvT, s_bias);
    // launch 1
    ln_kernel<<<TOK, 256>>>(x, ln1w, ln1b, h);
    // launch 2: fused QKV
    mma_gemm<0><<<gQKV, 256, GEMM_SMEM>>>(h, WqkvT, s_bias, nullptr, qkv, TOK, NQKV, DMODEL);
    // launch 3 (profiled): MMA flash attention
    attn_kernel<<<dim3((SEQ + 127) / 128, BATCH * HEADS), 256, ATTN_SMEM>>>(qkv, cb);
    // launch 4: Wo/W1/W2 transposes (needed from launch 5 on)
    transpose_w3<<<dim3(96, 96, 3), tb>>>(Wo, W1, W2, WoT, W1T, W2T);
    // launch 5: Wo GEMM + residual
    mma_gemm<1><<<gD, 256, GEMM_SMEM>>>(cb, WoT, bo, x, out, TOK, DMODEL, DMODEL);
    // launch 6
    ln_kernel<<<TOK, 256>>>(out, ln2w, ln2b, h);
    // launch 7: MLP up + GELU
    mma_gemm<2><<<gF, 256, GEMM_SMEM>>>(h, W1T, b1, nullptr, fb, TOK, FFDIM, DMODEL);
    // launch 8: MLP down + residual
    mma_gemm<1><<<gD, 256, GEMM_SMEM>>>(fb, W2T, b2, out, out, TOK, DMODEL, FFDIM);
}

// round 12
// speedup vs baseline: 2.3267x; 1.0058x over previous
#include <cuda_runtime.h>
#include <math.h>
#include <stdint.h>

#define TOK    18464         // B*S = 32*577
#define DMODEL 768
#define HEADS  12
#define DH     64
#define SEQ    577
#define BATCH  32
#define FFDIM  3072
#define NQKV   2304          // 3*DMODEL fused QKV output width

// ---------------- static scratch (no allocations allowed) ----------------
// g_big overlay: phase A [qkv (TOK*2304) | ctx (TOK*768)] ; phase B [ffn TOK*3072]
__device__ float g_big[(size_t)TOK * FFDIM];
__device__ float g_h  [(size_t)TOK * DMODEL];
// WqkvT [2304][768], WoT [768][768], W1T [3072][768], W2T [768][3072]
__device__ float g_wt [2304 * 768 + 768 * 768 + 3072 * 768 + 768 * 3072];
__device__ float g_bias[NQKV];

// ---------------- helpers ----------------
__device__ __forceinline__ uint32_t smem_u32(const void* p) {
    uint32_t a;
    asm("{ .reg .u64 t; cvta.to.shared.u64 t, %1; cvt.u32.u64 %0, t; }" : "=r"(a) : "l"(p));
    return a;
}
__device__ __forceinline__ float rn_tf32(float x) {
    uint32_t u;
    asm("cvt.rna.tf32.f32 %0, %1;" : "=r"(u) : "f"(x));
    return __uint_as_float(u);
}
__device__ __forceinline__ void cp16(uint32_t dst, const void* src, int sz) {
    asm volatile("cp.async.cg.shared.global [%0], [%1], 16, %2;"
                 :: "r"(dst), "l"(src), "r"(sz) : "memory");
}
__device__ __forceinline__ void cp_commit() {
    asm volatile("cp.async.commit_group;" ::: "memory");
}
template<int N>
__device__ __forceinline__ void cp_wait() {
    asm volatile("cp.async.wait_group %0;" :: "n"(N) : "memory");
}
__device__ __forceinline__ void mma_tf32(float* d, const float* a, const float* b) {
    asm volatile(
        "mma.sync.aligned.m16n8k8.row.col.f32.tf32.tf32.f32 "
        "{%0,%1,%2,%3}, {%4,%5,%6,%7}, {%8,%9}, {%0,%1,%2,%3};"
        : "+f"(d[0]), "+f"(d[1]), "+f"(d[2]), "+f"(d[3])
        : "r"(__float_as_uint(a[0])), "r"(__float_as_uint(a[1])),
          "r"(__float_as_uint(a[2])), "r"(__float_as_uint(a[3])),
          "r"(__float_as_uint(b[0])), "r"(__float_as_uint(b[1])));
}

// ---------------- LayerNorm (tf32-rounded output) ----------------
__global__ void ln_kernel(const float* __restrict__ x, const float* __restrict__ w,
                          const float* __restrict__ b, float* __restrict__ out) {
    int t = blockIdx.x;
    const float* xr = x + (size_t)t * DMODEL;
    float* orow = out + (size_t)t * DMODEL;
    float v[3];
    float s = 0.f, ss = 0.f;
#pragma unroll
    for (int i = 0; i < 3; i++) {
        v[i] = xr[threadIdx.x + i * 256];
        s += v[i]; ss += v[i] * v[i];
    }
    __shared__ float red[16];
#pragma unroll
    for (int o = 16; o; o >>= 1) {
        s  += __shfl_xor_sync(~0u, s,  o);
        ss += __shfl_xor_sync(~0u, ss, o);
    }
    int wid = threadIdx.x >> 5, lid = threadIdx.x & 31;
    if (lid == 0) { red[wid] = s; red[8 + wid] = ss; }
    __syncthreads();
    s = 0.f; ss = 0.f;
#pragma unroll
    for (int i = 0; i < 8; i++) { s += red[i]; ss += red[8 + i]; }
    float mean = s * (1.0f / DMODEL);
    float var  = ss * (1.0f / DMODEL) - mean * mean;
    float rstd = rsqrtf(var + 1e-5f);
#pragma unroll
    for (int i = 0; i < 3; i++) {
        int d = threadIdx.x + i * 256;
        orow[d] = rn_tf32((v[i] - mean) * rstd * w[d] + b[d]);
    }
}

// ---------------- fused QKV transpose: (H,768,64)x3 -> WqkvT[2304][768] + bias ----------------
__global__ void transpose_qkv(const float* __restrict__ Wq, const float* __restrict__ Wk,
                              const float* __restrict__ Wv,
                              const float* __restrict__ bq, const float* __restrict__ bk,
                              const float* __restrict__ bv,
                              float* __restrict__ WT, float* __restrict__ bias) {
    __shared__ float t[32][33];
    int n0 = blockIdx.x * 32, k0 = blockIdx.y * 32;
    int n = n0 + threadIdx.x;
    int proj = n / DMODEL;                  // uniform per block (768 % 32 == 0)
    int c = n - proj * DMODEL;
    const float* W = (proj == 0) ? Wq : (proj == 1) ? Wk : Wv;
    const float* Wp = W + (size_t)(c >> 6) * DMODEL * 64 + (c & 63);
#pragma unroll
    for (int j = 0; j < 4; j++)
        t[threadIdx.y + 8 * j][threadIdx.x] = Wp[(size_t)(k0 + threadIdx.y + 8 * j) * 64];
    if (blockIdx.y == 0 && threadIdx.y == 0) {
        const float* bb = (proj == 0) ? bq : (proj == 1) ? bk : bv;
        bias[n] = bb[c];
    }
    __syncthreads();
#pragma unroll
    for (int j = 0; j < 4; j++)
        WT[(size_t)(n0 + threadIdx.y + 8 * j) * DMODEL + k0 + threadIdx.x] =
            rn_tf32(t[threadIdx.x][threadIdx.y + 8 * j]);
}

// ---------------- Wo/W1/W2 transpose in one launch (z dispatch) ----------------
__global__ void transpose_w3(const float* __restrict__ Wo, const float* __restrict__ W1,
                             const float* __restrict__ W2,
                             float* __restrict__ WoT, float* __restrict__ W1T,
                             float* __restrict__ W2T) {
    int z = blockIdx.z;
    const float* W; float* WT; int K, N;
    if (z == 0)      { W = Wo; WT = WoT; K = 768;  N = 768;  }
    else if (z == 1) { W = W1; WT = W1T; K = 768;  N = 3072; }
    else             { W = W2; WT = W2T; K = 3072; N = 768;  }
    int n0 = blockIdx.x * 32, k0 = blockIdx.y * 32;
    if (n0 >= N || k0 >= K) return;
    __shared__ float t[32][33];
#pragma unroll
    for (int j = 0; j < 4; j++)
        t[threadIdx.y + 8 * j][threadIdx.x] =
            W[(size_t)(k0 + threadIdx.y + 8 * j) * N + n0 + threadIdx.x];
    __syncthreads();
#pragma unroll
    for (int j = 0; j < 4; j++)
        WT[(size_t)(n0 + threadIdx.y + 8 * j) * K + k0 + threadIdx.x] =
            rn_tf32(t[threadIdx.x][threadIdx.y + 8 * j]);
}

// ---------------- TF32 warp-MMA GEMM: C[M,N] = A[M,K] @ Bt[N,K]^T ----------------
// Tile 128x128x32, 8 warps (2x4), warp tile 64x32 = 4x4 m16n8k8.
// 3-stage cp.async pipeline, ONE __syncthreads per K-chunk.
// k-slot relabeling -> float2 fragment loads; row pad 40 (pad%32==8) makes
// per-phase bank index 8g+2t4: conflict-free LDS.64.
// EPI: 0 = +bias ; 1 = +bias+resid ; 2 = gelu(+bias), tf32-rounded
#define RPAD 40
#define STAGE_B 40960u            // (128+128) rows * 40 floats * 4B
#define STAGE_F 10240             // floats per stage
#define GEMM_SMEM (3 * 40960)     // 122880

template<int EPI>
__global__ __launch_bounds__(256, 2)
void mma_gemm(const float* __restrict__ A, const float* __restrict__ Bt,
              const float* __restrict__ bias, const float* __restrict__ resid,
              float* __restrict__ C, int M, int N, int K) {
    extern __shared__ float sm[];
    uint32_t sb = smem_u32(sm);
    int tid = threadIdx.x;
    int wid = tid >> 5, lane = tid & 31;
    int g = lane >> 2, t4 = lane & 3;
    int wm = wid >> 2, wn = wid & 3;
    int m0 = blockIdx.y * 128, n0 = blockIdx.x * 128;

    int lrow = tid >> 1;
    int lcol = (tid & 1) * 16;
    bool aok = (m0 + lrow) < M;
    const float* Aptr = aok ? (A + (size_t)(m0 + lrow) * K + lcol) : A;
    const float* Bptr = Bt + (size_t)(n0 + lrow) * K + lcol;
    int asz = aok ? 16 : 0;
    uint32_t sa = sb + (uint32_t)(lrow * RPAD + lcol) * 4;
    uint32_t sbB = sa + 128 * RPAD * 4;       // +20480

    float acc[4][4][4];
#pragma unroll
    for (int mi = 0; mi < 4; mi++)
#pragma unroll
        for (int ni = 0; ni < 4; ni++)
#pragma unroll
            for (int j = 0; j < 4; j++) acc[mi][ni][j] = 0.f;

    const int nch = K / 32;

#pragma unroll
    for (int p = 0; p < 2; p++) {
        uint32_t off = p * STAGE_B;
#pragma unroll
        for (int q = 0; q < 4; q++) {
            cp16(sa  + off + q * 16, Aptr + p * 32 + q * 4, asz);
            cp16(sbB + off + q * 16, Bptr + p * 32 + q * 4, 16);
        }
        cp_commit();
    }

    int stage = 0;
    for (int i = 0; i < nch; i++) {
        if (i == nch - 1) cp_wait<0>(); else cp_wait<1>();
        __syncthreads();
        if (i + 2 < nch) {
            int ps = (stage + 2 >= 3) ? stage - 1 : stage + 2;   // (stage+2)%3
            uint32_t off = (uint32_t)ps * STAGE_B;
#pragma unroll
            for (int q = 0; q < 4; q++) {
                cp16(sa  + off + q * 16, Aptr + (i + 2) * 32 + q * 4, asz);
                cp16(sbB + off + q * 16, Bptr + (i + 2) * 32 + q * 4, 16);
            }
            cp_commit();
        }

        const float* As = sm + stage * STAGE_F;
        const float* Bs = As + 128 * RPAD;
#pragma unroll
        for (int kk = 0; kk < 4; kk++) {
            float af[4][4], bf[4][2];
#pragma unroll
            for (int mi = 0; mi < 4; mi++) {
                int r = wm * 64 + mi * 16 + g;
                float2 lo = *(const float2*)&As[r * RPAD + kk * 8 + 2 * t4];
                float2 hi = *(const float2*)&As[(r + 8) * RPAD + kk * 8 + 2 * t4];
                af[mi][0] = lo.x; af[mi][1] = hi.x; af[mi][2] = lo.y; af[mi][3] = hi.y;
            }
#pragma unroll
            for (int ni = 0; ni < 4; ni++) {
                int c = wn * 32 + ni * 8 + g;
                float2 bb = *(const float2*)&Bs[c * RPAD + kk * 8 + 2 * t4];
                bf[ni][0] = bb.x; bf[ni][1] = bb.y;
            }
#pragma unroll
            for (int mi = 0; mi < 4; mi++)
#pragma unroll
                for (int ni = 0; ni < 4; ni++)
                    mma_tf32(acc[mi][ni], af[mi], bf[ni]);
        }
        stage = (stage + 1 == 3) ? 0 : stage + 1;
    }

    // epilogue
#pragma unroll
    for (int mi = 0; mi < 4; mi++) {
        int r1 = m0 + wm * 64 + mi * 16 + g;
        int r2 = r1 + 8;
#pragma unroll
        for (int ni = 0; ni < 4; ni++) {
            int col = n0 + wn * 32 + ni * 8 + 2 * t4;
            float2 bs = *(const float2*)(bias + col);
#pragma unroll
            for (int hrow = 0; hrow < 2; hrow++) {
                int r = hrow ? r2 : r1;
                if (r < M) {
                    float v0 = acc[mi][ni][hrow * 2 + 0] + bs.x;
                    float v1 = acc[mi][ni][hrow * 2 + 1] + bs.y;
                    if (EPI == 1) {
                        float2 rv = *(const float2*)(resid + (size_t)r * N + col);
                        v0 += rv.x; v1 += rv.y;
                    }
                    if (EPI == 2) {
                        v0 = rn_tf32(0.5f * v0 * (1.0f + erff(v0 * 0.70710678f)));
                        v1 = rn_tf32(0.5f * v1 * (1.0f + erff(v1 * 0.70710678f)));
                    }
                    *(float2*)(C + (size_t)r * N + col) = make_float2(v0, v1);
                }
            }
        }
    }
}

// ---------------- MMA flash attention over fused qkv [TOK][2304] ----------------
// Block = 128 q-rows of one (b,h). 8 warps, warp = 16 rows x 64 cols.
// Qs/Ks pad 72 (pad%32==8 -> conflict-free float2 frag loads);
// Vs pad 68 (scalar loads 8t4+g bijective -> conflict-free).
#define QPAD 72
#define VPAD 68
#define ATTN_SMEM ((128 * QPAD + 64 * QPAD + 64 * VPAD) * 4)   // 72704 B

__global__ __launch_bounds__(256, 2)
void attn_kernel(const float* __restrict__ qkv, float* __restrict__ ctx) {
    extern __shared__ float smf[];
    float* Qs = smf;                     // [128][72]
    float* Ks = smf + 128 * QPAD;        // [64][72]  row = key, col = d
    float* Vs = Ks + 64 * QPAD;          // [64][68]  row = key, col = d
    int bh = blockIdx.y;
    int b = bh / HEADS, h = bh % HEADS;
    int q0 = blockIdx.x * 128;
    int tid = threadIdx.x;
    int wid = tid >> 5, lane = tid & 31;
    int g = lane >> 2, t4 = lane & 3;
    size_t baseq = (size_t)b * SEQ * NQKV + h * DH;   // q +0, k +768, v +1536
    size_t baseo = (size_t)b * SEQ * DMODEL + h * DH;

    // load Q tile (rounded)
    {
        int r = tid >> 1;
        int c0 = (tid & 1) * 32;
        int s = q0 + r;
        float* dst = Qs + r * QPAD + c0;
        if (s < SEQ) {
            const float* qp = qkv + baseq + (size_t)s * NQKV + c0;
#pragma unroll
            for (int j = 0; j < 8; j++) {
                float4 v = *(const float4*)(qp + j * 4);
                *(float4*)(dst + j * 4) = make_float4(rn_tf32(v.x), rn_tf32(v.y),
                                                      rn_tf32(v.z), rn_tf32(v.w));
            }
        } else {
#pragma unroll
            for (int j = 0; j < 8; j++)
                *(float4*)(dst + j * 4) = make_float4(0.f, 0.f, 0.f, 0.f);
        }
    }

    float mr[2] = {-1e30f, -1e30f};
    float lr[2] = {0.f, 0.f};
    float O[8][4];
#pragma unroll
    for (int nt = 0; nt < 8; nt++)
#pragma unroll
        for (int j = 0; j < 4; j++) O[nt][j] = 0.f;

    int rA = wid * 16 + g;
    const int NT = (SEQ + 63) / 64;   // 10
    for (int kt = 0; kt < NT; kt++) {
        __syncthreads();
        // load K,V tile (rounded)
        {
            int r = tid >> 2;
            int c0 = (tid & 3) * 16;
            int s = kt * 64 + r;
            float* dk = Ks + r * QPAD + c0;
            float* dv = Vs + r * VPAD + c0;
            if (s < SEQ) {
                const float* kp = qkv + baseq + 768  + (size_t)s * NQKV + c0;
                const float* vp = qkv + baseq + 1536 + (size_t)s * NQKV + c0;
#pragma unroll
                for (int j = 0; j < 4; j++) {
                    float4 kv = *(const float4*)(kp + j * 4);
                    *(float4*)(dk + j * 4) = make_float4(rn_tf32(kv.x), rn_tf32(kv.y),
                                                         rn_tf32(kv.z), rn_tf32(kv.w));
                    float4 vv = *(const float4*)(vp + j * 4);
                    *(float4*)(dv + j * 4) = make_float4(rn_tf32(vv.x), rn_tf32(vv.y),
                                                         rn_tf32(vv.z), rn_tf32(vv.w));
                }
            } else {
#pragma unroll
                for (int j = 0; j < 4; j++) {
                    *(float4*)(dk + j * 4) = make_float4(0.f, 0.f, 0.f, 0.f);
                    *(float4*)(dv + j * 4) = make_float4(0.f, 0.f, 0.f, 0.f);
                }
            }
        }
        __syncthreads();

        // S = Q K^T  (warp: 16 rows x 64 keys)
        float S[8][4];
#pragma unroll
        for (int nt = 0; nt < 8; nt++)
#pragma unroll
            for (int j = 0; j < 4; j++) S[nt][j] = 0.f;
#pragma unroll
        for (int kk = 0; kk < 8; kk++) {
            float2 alo = *(const float2*)&Qs[rA * QPAD + kk * 8 + 2 * t4];
            float2 ahi = *(const float2*)&Qs[(rA + 8) * QPAD + kk * 8 + 2 * t4];
            float a[4] = {alo.x, ahi.x, alo.y, ahi.y};
#pragma unroll
            for (int nt = 0; nt < 8; nt++) {
                float2 bb = *(const float2*)&Ks[(nt * 8 + g) * QPAD + kk * 8 + 2 * t4];
                float bf[2] = {bb.x, bb.y};
                mma_tf32(S[nt], a, bf);
            }
        }

        // scale + mask + online softmax (rows g and g+8 of this warp)
#pragma unroll
        for (int nt = 0; nt < 8; nt++) {
            int c0v = kt * 64 + nt * 8 + 2 * t4;
            bool v0 = c0v < SEQ, v1 = (c0v + 1) < SEQ;
            S[nt][0] = v0 ? S[nt][0] * 0.125f : -1e30f;
            S[nt][1] = v1 ? S[nt][1] * 0.125f : -1e30f;
            S[nt][2] = v0 ? S[nt][2] * 0.125f : -1e30f;
            S[nt][3] = v1 ? S[nt][3] * 0.125f : -1e30f;
        }
        float mx0 = -1e30f, mx1 = -1e30f;
#pragma unroll
        for (int nt = 0; nt < 8; nt++) {
            mx0 = fmaxf(mx0, fmaxf(S[nt][0], S[nt][1]));
            mx1 = fmaxf(mx1, fmaxf(S[nt][2], S[nt][3]));
        }
#pragma unroll
        for (int o = 1; o < 4; o <<= 1) {
            mx0 = fmaxf(mx0, __shfl_xor_sync(~0u, mx0, o));
            mx1 = fmaxf(mx1, __shfl_xor_sync(~0u, mx1, o));
        }
        float mn0 = fmaxf(mr[0], mx0), mn1 = fmaxf(mr[1], mx1);
        float corr0 = __expf(mr[0] - mn0), corr1 = __expf(mr[1] - mn1);
        mr[0] = mn0; mr[1] = mn1;
        float ls0 = 0.f, ls1 = 0.f;
#pragma unroll
        for (int nt = 0; nt < 8; nt++) {
            S[nt][0] = rn_tf32(__expf(S[nt][0] - mn0));
            S[nt][1] = rn_tf32(__expf(S[nt][1] - mn0));
            S[nt][2] = rn_tf32(__expf(S[nt][2] - mn1));
            S[nt][3] = rn_tf32(__expf(S[nt][3] - mn1));
            ls0 += S[nt][0] + S[nt][1];
            ls1 += S[nt][2] + S[nt][3];
        }
#pragma unroll
        for (int o = 1; o < 4; o <<= 1) {
            ls0 += __shfl_xor_sync(~0u, ls0, o);
            ls1 += __shfl_xor_sync(~0u, ls1, o);
        }
        lr[0] = lr[0] * corr0 + ls0;
        lr[1] = lr[1] * corr1 + ls1;
#pragma unroll
        for (int nt = 0; nt < 8; nt++) {
            O[nt][0] *= corr0; O[nt][1] *= corr0;
            O[nt][2] *= corr1; O[nt][3] *= corr1;
        }

        // O += P V : contraction over keys; kk-th key group = S[kk] fragments
#pragma unroll
        for (int kk = 0; kk < 8; kk++) {
            float a[4] = {S[kk][0], S[kk][2], S[kk][1], S[kk][3]};
#pragma unroll
            for (int nt = 0; nt < 8; nt++) {
                float bf[2];
                bf[0] = Vs[(kk * 8 + 2 * t4) * VPAD + nt * 8 + g];
                bf[1] = Vs[(kk * 8 + 2 * t4 + 1) * VPAD + nt * 8 + g];
                mma_tf32(O[nt], a, bf);
            }
        }
    }

    // write ctx (rounded for the Wo GEMM)
    float inv0 = 1.0f / lr[0], inv1 = 1.0f / lr[1];
    int s0 = q0 + wid * 16 + g;
    int s1 = s0 + 8;
#pragma unroll
    for (int nt = 0; nt < 8; nt++) {
        int col = nt * 8 + 2 * t4;
        if (s0 < SEQ)
            *(float2*)(ctx + baseo + (size_t)s0 * DMODEL + col) =
                make_float2(rn_tf32(O[nt][0] * inv0), rn_tf32(O[nt][1] * inv0));
        if (s1 < SEQ)
            *(float2*)(ctx + baseo + (size_t)s1 * DMODEL + col) =
                make_float2(rn_tf32(O[nt][2] * inv1), rn_tf32(O[nt][3] * inv1));
    }
}

// ---------------- launch ----------------
extern "C" void kernel_launch(void* const* d_in, const int* in_sizes, int n_in,
                              void* d_out, int out_size) {
    const float* x    = (const float*)d_in[0];
    const float* ln1w = (const float*)d_in[1];
    const float* ln1b = (const float*)d_in[2];
    const float* Wq   = (const float*)d_in[3];
    const float* bq   = (const float*)d_in[4];
    const float* Wk   = (const float*)d_in[5];
    const float* bk   = (const float*)d_in[6];
    const float* Wv   = (const float*)d_in[7];
    const float* bv   = (const float*)d_in[8];
    const float* Wo   = (const float*)d_in[9];
    const float* bo   = (const float*)d_in[10];
    const float* ln2w = (const float*)d_in[11];
    const float* ln2b = (const float*)d_in[12];
    const float* W1   = (const float*)d_in[13];
    const float* b1   = (const float*)d_in[14];
    const float* W2   = (const float*)d_in[15];
    const float* b2   = (const float*)d_in[16];
    float* out = (float*)d_out;

    static float* s_big = nullptr;
    static float* s_h   = nullptr;
    static float* s_wt  = nullptr;
    static float* s_bias = nullptr;
    if (!s_big) {
        cudaGetSymbolAddress((void**)&s_big, g_big);
        cudaGetSymbolAddress((void**)&s_h,   g_h);
        cudaGetSymbolAddress((void**)&s_wt,  g_wt);
        cudaGetSymbolAddress((void**)&s_bias, g_bias);
        cudaFuncSetAttribute(mma_gemm<0>, cudaFuncAttributeMaxDynamicSharedMemorySize, GEMM_SMEM);
        cudaFuncSetAttribute(mma_gemm<1>, cudaFuncAttributeMaxDynamicSharedMemorySize, GEMM_SMEM);
        cudaFuncSetAttribute(mma_gemm<2>, cudaFuncAttributeMaxDynamicSharedMemorySize, GEMM_SMEM);
        cudaFuncSetAttribute(attn_kernel, cudaFuncAttributeMaxDynamicSharedMemorySize, ATTN_SMEM);
    }
    const size_t TD = (size_t)TOK * DMODEL;
    float* h   = s_h;
    float* qkv = s_big;                 // [TOK][2304]
    float* cb  = s_big + 3 * TD;        // ctx [TOK][768]
    float* fb  = s_big;                 // phase B ffn [TOK][3072]

    float* WqkvT = s_wt;                                   // [2304][768]
    float* WoT   = s_wt + 2304 * 768;                      // [768][768]
    float* W1T   = WoT + 768 * 768;                        // [3072][768]
    float* W2T   = W1T + 3072 * 768;                       // [768][3072]

    dim3 tb(32, 8);
    dim3 gQKV(NQKV / 128, (TOK + 127) / 128);
    dim3 gD(DMODEL / 128, (TOK + 127) / 128);
    dim3 gF(FFDIM / 128, (TOK + 127) / 128);

    // launch 0
    transpose_qkv<<<dim3(NQKV / 32, DMODEL / 32), tb>>>(Wq, Wk, Wv, bq, bk, bv, WqkvT, s_bias);
    // launch 1
    ln_kernel<<<TOK, 256>>>(x, ln1w, ln1b, h);
    // launch 2: fused QKV
    mma_gemm<0><<<gQKV, 256, GEMM_SMEM>>>(h, WqkvT, s_bias, nullptr, qkv, TOK, NQKV, DMODEL);
    // launch 3 (profiled): MMA flash attention
    attn_kernel<<<dim3((SEQ + 127) / 128, BATCH * HEADS), 256, ATTN_SMEM>>>(qkv, cb);
    // launch 4: Wo/W1/W2 transposes (needed from launch 5 on)
    transpose_w3<<<dim3(96, 96, 3), tb>>>(Wo, W1, W2, WoT, W1T, W2T);
    // launch 5: Wo GEMM + residual
    mma_gemm<1><<<gD, 256, GEMM_SMEM>>>(cb, WoT, bo, x, out, TOK, DMODEL, DMODEL);
    // launch 6
    ln_kernel<<<TOK, 256>>>(out, ln2w, ln2b, h);
    // launch 7: MLP up + GELU
    mma_gemm<2><<<gF, 256, GEMM_SMEM>>>(h, W1T, b1, nullptr, fb, TOK, FFDIM, DMODEL);
    // launch 8: MLP down + residual
    mma_gemm<1><<<gD, 256, GEMM_SMEM>>>(fb, W2T, b2, out, out, TOK, DMODEL, FFDIM);
}